// round 1
// baseline (speedup 1.0000x reference)
#include <cuda_runtime.h>
#include <math.h>

// Problem constants
#define Ld  1024
#define Bd  4
#define Fd  512
#define Hd  8
#define Kd  64
#define Md  2048          // Lk + Lfuse
#define HBd (Hd*Bd)       // 32
#define HFd (Hd*Fd)       // 4096

// ---------------- scratch (device globals; no allocs allowed) ----------------
__device__ float g_RQ [HBd*Ld*Kd];             // (h*B+b, L, K)  8 MB
__device__ float g_TQ [HBd*Ld*Kd];
__device__ float g_FK [HBd*Md*Kd];             // (h*B+b, M, K) 16 MB
__device__ float g_FK1[HBd*Md*Kd];
__device__ float g_Srgb[(size_t)HBd*Ld*Md];    // raw dots, 256 MB
__device__ float g_St  [(size_t)HBd*Ld*Md];
__device__ float g_stats[HBd*Ld*6];            // m_rgb,sum_rgb,m_t,sum_t,m_x,sum_x

// =====================================================================
// Kernel 1: projection + per-head L2 norm.
//   out[(h*B+b)*Lx + l][k] = normalize_k( sum_f X[t=(l,b)][f] * W[h*64+k][f] + bias )
//   X rows: t < rows0 -> src0, else src1 (handles concat along L).
// grid: (Lx*B/64, H), block 256
// =====================================================================
__global__ __launch_bounds__(256)
void proj_kernel(const float* __restrict__ src0, const float* __restrict__ src1,
                 int rows0, int Lx,
                 const float* __restrict__ Wm, const float* __restrict__ bias,
                 int dst)
{
    __shared__ float Xs[32][68];
    __shared__ float Ws[32][68];
    float* out = (dst == 0) ? g_RQ : (dst == 1) ? g_TQ : (dst == 2) ? g_FK : g_FK1;

    const int h = blockIdx.y;
    const int rowBase = blockIdx.x * 64;
    const int tid = threadIdx.x;
    const int tx = tid & 15, ty = tid >> 4;

    float acc[4][4] = {};

    for (int k0 = 0; k0 < Fd; k0 += 32) {
        #pragma unroll
        for (int p = 0; p < 2; p++) {
            int id = tid + p * 256;         // 0..511
            int r  = id >> 3;               // 0..63
            int c4 = (id & 7) * 4;          // 0..28
            int gr = rowBase + r;
            const float* xr = (gr < rows0) ? (src0 + (size_t)gr * Fd)
                                           : (src1 + (size_t)(gr - rows0) * Fd);
            float4 v = *reinterpret_cast<const float4*>(xr + k0 + c4);
            Xs[c4+0][r] = v.x; Xs[c4+1][r] = v.y; Xs[c4+2][r] = v.z; Xs[c4+3][r] = v.w;
            float4 w = *reinterpret_cast<const float4*>(Wm + (size_t)(h*64 + r) * Fd + k0 + c4);
            Ws[c4+0][r] = w.x; Ws[c4+1][r] = w.y; Ws[c4+2][r] = w.z; Ws[c4+3][r] = w.w;
        }
        __syncthreads();
        #pragma unroll
        for (int kk = 0; kk < 32; kk++) {
            float4 a = *reinterpret_cast<const float4*>(&Xs[kk][ty*4]);
            float4 b = *reinterpret_cast<const float4*>(&Ws[kk][tx*4]);
            float av[4] = {a.x, a.y, a.z, a.w};
            float bv[4] = {b.x, b.y, b.z, b.w};
            #pragma unroll
            for (int i = 0; i < 4; i++)
                #pragma unroll
                for (int j = 0; j < 4; j++)
                    acc[i][j] += av[i] * bv[j];
        }
        __syncthreads();
    }

    // bias (zeros per setup, but keep for fidelity)
    #pragma unroll
    for (int j = 0; j < 4; j++) {
        float bb = bias[h*64 + tx*4 + j];
        #pragma unroll
        for (int i = 0; i < 4; i++) acc[i][j] += bb;
    }

    // per-row L2 norm over the 64 head columns (reduce over 16 tx lanes)
    #pragma unroll
    for (int i = 0; i < 4; i++) {
        float s = 0.f;
        #pragma unroll
        for (int j = 0; j < 4; j++) s += acc[i][j] * acc[i][j];
        s += __shfl_xor_sync(0xffffffffu, s, 1);
        s += __shfl_xor_sync(0xffffffffu, s, 2);
        s += __shfl_xor_sync(0xffffffffu, s, 4);
        s += __shfl_xor_sync(0xffffffffu, s, 8);
        float inv = 1.0f / fmaxf(sqrtf(s), 1e-12f);
        int gr = rowBase + ty*4 + i;
        int l  = gr / Bd, b = gr % Bd;
        float4 o = make_float4(acc[i][0]*inv, acc[i][1]*inv, acc[i][2]*inv, acc[i][3]*inv);
        *reinterpret_cast<float4*>(out + ((size_t)(h*Bd + b) * Lx + l) * Kd + tx*4) = o;
    }
}

// =====================================================================
// Kernel 2: scores  S[hb][l][m] = sum_k Q[hb][l][k] * Kn[hb][m][k]   (K=64, one pass)
// grid: (M/64, L/64, HB), block 256
// =====================================================================
__global__ __launch_bounds__(256)
void dot_kernel(int sel)
{
    __shared__ float Qs[64][68];
    __shared__ float Ks[64][68];
    const float* Qn = sel ? g_TQ  : g_RQ;
    const float* Kn = sel ? g_FK1 : g_FK;
    float*       S  = sel ? g_St  : g_Srgb;

    const int hb = blockIdx.z;
    const int mBase = blockIdx.x * 64, lBase = blockIdx.y * 64;
    const int tid = threadIdx.x;
    const int tx = tid & 15, ty = tid >> 4;
    const float* Qp = Qn + (size_t)hb * Ld * Kd;
    const float* Kp = Kn + (size_t)hb * Md * Kd;

    #pragma unroll
    for (int p = 0; p < 4; p++) {
        int id = tid + p * 256;        // 0..1023
        int r  = id >> 4;              // 0..63
        int c4 = (id & 15) * 4;        // 0..60
        float4 q = *reinterpret_cast<const float4*>(Qp + (size_t)(lBase + r) * Kd + c4);
        Qs[c4+0][r] = q.x; Qs[c4+1][r] = q.y; Qs[c4+2][r] = q.z; Qs[c4+3][r] = q.w;
        float4 k = *reinterpret_cast<const float4*>(Kp + (size_t)(mBase + r) * Kd + c4);
        Ks[c4+0][r] = k.x; Ks[c4+1][r] = k.y; Ks[c4+2][r] = k.z; Ks[c4+3][r] = k.w;
    }
    __syncthreads();

    float acc[4][4] = {};
    #pragma unroll 16
    for (int kk = 0; kk < 64; kk++) {
        float4 a = *reinterpret_cast<const float4*>(&Qs[kk][ty*4]);
        float4 b = *reinterpret_cast<const float4*>(&Ks[kk][tx*4]);
        float av[4] = {a.x, a.y, a.z, a.w};
        float bv[4] = {b.x, b.y, b.z, b.w};
        #pragma unroll
        for (int i = 0; i < 4; i++)
            #pragma unroll
            for (int j = 0; j < 4; j++)
                acc[i][j] += av[i] * bv[j];
    }

    #pragma unroll
    for (int i = 0; i < 4; i++) {
        int l = lBase + ty*4 + i;
        float4 o = make_float4(acc[i][0], acc[i][1], acc[i][2], acc[i][3]);
        *reinterpret_cast<float4*>(S + ((size_t)hb * Ld + l) * Md + mBase + tx*4) = o;
    }
}

// =====================================================================
// Kernel 3: per-row softmax stats for the three affinities.
//   streams: 100*s_rgb, 100*s_t, s_rgb*s_t
// grid: HB*L blocks of 256
// =====================================================================
__global__ __launch_bounds__(256)
void stats_kernel()
{
    const int row = blockIdx.x;
    const float* sr = g_Srgb + (size_t)row * Md;
    const float* st = g_St   + (size_t)row * Md;
    const int tid = threadIdx.x;
    const int lane = tid & 31, warp = tid >> 5;
    __shared__ float sm[8][6];

    float m1 = -1e30f, m2 = -1e30f, m3 = -1e30f;
    for (int i = tid; i < Md; i += 256) {
        float a = sr[i], b = st[i];
        m1 = fmaxf(m1, 100.f * a);
        m2 = fmaxf(m2, 100.f * b);
        m3 = fmaxf(m3, a * b);
    }
    #pragma unroll
    for (int o = 16; o > 0; o >>= 1) {
        m1 = fmaxf(m1, __shfl_xor_sync(0xffffffffu, m1, o));
        m2 = fmaxf(m2, __shfl_xor_sync(0xffffffffu, m2, o));
        m3 = fmaxf(m3, __shfl_xor_sync(0xffffffffu, m3, o));
    }
    if (lane == 0) { sm[warp][0] = m1; sm[warp][1] = m2; sm[warp][2] = m3; }
    __syncthreads();
    m1 = m2 = m3 = -1e30f;
    #pragma unroll
    for (int w = 0; w < 8; w++) {
        m1 = fmaxf(m1, sm[w][0]); m2 = fmaxf(m2, sm[w][1]); m3 = fmaxf(m3, sm[w][2]);
    }

    float s1 = 0.f, s2 = 0.f, s3 = 0.f;
    for (int i = tid; i < Md; i += 256) {
        float a = sr[i], b = st[i];
        s1 += __expf(100.f * a - m1);
        s2 += __expf(100.f * b - m2);
        s3 += __expf(a * b - m3);
    }
    #pragma unroll
    for (int o = 16; o > 0; o >>= 1) {
        s1 += __shfl_xor_sync(0xffffffffu, s1, o);
        s2 += __shfl_xor_sync(0xffffffffu, s2, o);
        s3 += __shfl_xor_sync(0xffffffffu, s3, o);
    }
    __syncthreads();
    if (lane == 0) { sm[warp][3] = s1; sm[warp][4] = s2; sm[warp][5] = s3; }
    __syncthreads();
    if (tid == 0) {
        s1 = s2 = s3 = 0.f;
        #pragma unroll
        for (int w = 0; w < 8; w++) { s1 += sm[w][3]; s2 += sm[w][4]; s3 += sm[w][5]; }
        float* o = g_stats + (size_t)row * 6;
        o[0] = m1; o[1] = s1; o[2] = m2; o[3] = s2; o[4] = m3; o[5] = s3;
    }
}

// =====================================================================
// Kernel 4: fused attend. Per (h,b, l-tile, f-tile): stream M in tiles of 32,
// build the three unnormalized P tiles with __expf on the fly, and accumulate
// all four outputs against rv/tv tiles. 1/sum folded into epilogue.
// grid: (F/64, L/64, HB), block 256
// =====================================================================
__global__ __launch_bounds__(256, 2)
void attend_kernel(const float* __restrict__ rgbvalue,
                   const float* __restrict__ tvalue,
                   const float* __restrict__ fusevalue,
                   float* __restrict__ out)
{
    __shared__ float Pr[32][68], Pt[32][68], Px[32][68];
    __shared__ float Vr[32][68], Vt[32][68];

    const int hb = blockIdx.z;
    const int h  = hb / Bd, b = hb % Bd;
    const int fBase = blockIdx.x * 64, lBase = blockIdx.y * 64;
    const int tid = threadIdx.x;
    const int tx = tid & 15, ty = tid >> 4;

    const float* srp = g_Srgb + ((size_t)hb * Ld + lBase) * Md;
    const float* stp = g_St   + ((size_t)hb * Ld + lBase) * Md;

    float a0[4][4] = {}, a1[4][4] = {}, a2[4][4] = {}, a3[4][4] = {};

    for (int m0 = 0; m0 < Md; m0 += 32) {
        // P tiles: rows 0..63 (l), cols m0..m0+31, stored transposed [m][l]
        #pragma unroll
        for (int p = 0; p < 2; p++) {
            int id = tid + p * 256;        // 0..511
            int r  = id >> 3;              // 0..63
            int c4 = (id & 7) * 4;
            const float* stw = g_stats + ((size_t)hb * Ld + lBase + r) * 6;
            float m1 = stw[0], m2 = stw[2], m3 = stw[4];
            float4 sa = *reinterpret_cast<const float4*>(srp + (size_t)r * Md + m0 + c4);
            float4 sb = *reinterpret_cast<const float4*>(stp + (size_t)r * Md + m0 + c4);
            Pr[c4+0][r] = __expf(100.f*sa.x - m1);
            Pr[c4+1][r] = __expf(100.f*sa.y - m1);
            Pr[c4+2][r] = __expf(100.f*sa.z - m1);
            Pr[c4+3][r] = __expf(100.f*sa.w - m1);
            Pt[c4+0][r] = __expf(100.f*sb.x - m2);
            Pt[c4+1][r] = __expf(100.f*sb.y - m2);
            Pt[c4+2][r] = __expf(100.f*sb.z - m2);
            Pt[c4+3][r] = __expf(100.f*sb.w - m2);
            Px[c4+0][r] = __expf(sa.x*sb.x - m3);
            Px[c4+1][r] = __expf(sa.y*sb.y - m3);
            Px[c4+2][r] = __expf(sa.z*sb.z - m3);
            Px[c4+3][r] = __expf(sa.w*sb.w - m3);
        }
        // V tiles: rows m0..m0+31 (m), cols fBase..fBase+63
        #pragma unroll
        for (int p = 0; p < 2; p++) {
            int id = tid + p * 256;        // 0..511
            int r  = id >> 4;              // 0..31
            int c4 = (id & 15) * 4;
            int m  = m0 + r;
            const float* vr = (m < Ld) ? rgbvalue + ((size_t)m * Bd + b) * Fd
                                       : fusevalue + ((size_t)(m - Ld) * Bd + b) * Fd;
            const float* vt = (m < Ld) ? tvalue   + ((size_t)m * Bd + b) * Fd
                                       : fusevalue + ((size_t)(m - Ld) * Bd + b) * Fd;
            *reinterpret_cast<float4*>(&Vr[r][c4]) = *reinterpret_cast<const float4*>(vr + fBase + c4);
            *reinterpret_cast<float4*>(&Vt[r][c4]) = *reinterpret_cast<const float4*>(vt + fBase + c4);
        }
        __syncthreads();

        #pragma unroll 8
        for (int kk = 0; kk < 32; kk++) {
            float4 pr = *reinterpret_cast<const float4*>(&Pr[kk][ty*4]);
            float4 pt = *reinterpret_cast<const float4*>(&Pt[kk][ty*4]);
            float4 px = *reinterpret_cast<const float4*>(&Px[kk][ty*4]);
            float4 vr = *reinterpret_cast<const float4*>(&Vr[kk][tx*4]);
            float4 vt = *reinterpret_cast<const float4*>(&Vt[kk][tx*4]);
            float prv[4] = {pr.x, pr.y, pr.z, pr.w};
            float ptv[4] = {pt.x, pt.y, pt.z, pt.w};
            float pxv[4] = {px.x, px.y, px.z, px.w};
            float vrv[4] = {vr.x, vr.y, vr.z, vr.w};
            float vtv[4] = {vt.x, vt.y, vt.z, vt.w};
            #pragma unroll
            for (int i = 0; i < 4; i++)
                #pragma unroll
                for (int j = 0; j < 4; j++) {
                    a0[i][j] += prv[i] * vrv[j];   // self_rgb
                    a1[i][j] += ptv[i] * vtv[j];   // self_t
                    a2[i][j] += pxv[i] * vtv[j];   // cross_rgb
                    a3[i][j] += pxv[i] * vrv[j];   // cross_t
                }
        }
        __syncthreads();
    }

    const size_t OSZ = (size_t)Ld * Bd * HFd;
    #pragma unroll
    for (int i = 0; i < 4; i++) {
        int l = lBase + ty*4 + i;
        const float* stw = g_stats + ((size_t)hb * Ld + l) * 6;
        float i1 = 1.f / stw[1], i2 = 1.f / stw[3], i3 = 1.f / stw[5];
        size_t base = ((size_t)l * Bd + b) * HFd + (size_t)h * Fd + fBase + tx*4;
        float4 o0 = make_float4(a0[i][0]*i1, a0[i][1]*i1, a0[i][2]*i1, a0[i][3]*i1);
        float4 o1 = make_float4(a1[i][0]*i2, a1[i][1]*i2, a1[i][2]*i2, a1[i][3]*i2);
        float4 o2 = make_float4(a2[i][0]*i3, a2[i][1]*i3, a2[i][2]*i3, a2[i][3]*i3);
        float4 o3 = make_float4(a3[i][0]*i3, a3[i][1]*i3, a3[i][2]*i3, a3[i][3]*i3);
        *reinterpret_cast<float4*>(out + 0*OSZ + base) = o0;
        *reinterpret_cast<float4*>(out + 1*OSZ + base) = o1;
        *reinterpret_cast<float4*>(out + 2*OSZ + base) = o2;
        *reinterpret_cast<float4*>(out + 3*OSZ + base) = o3;
    }
}

// =====================================================================
extern "C" void kernel_launch(void* const* d_in, const int* in_sizes, int n_in,
                              void* d_out, int out_size)
{
    const float* rgbquery  = (const float*)d_in[0];
    const float* rgbkey    = (const float*)d_in[1];
    const float* rgbvalue  = (const float*)d_in[2];
    const float* tquery    = (const float*)d_in[3];
    const float* tkey      = (const float*)d_in[4];
    const float* tvalue    = (const float*)d_in[5];
    const float* fusekey   = (const float*)d_in[6];
    const float* fusevalue = (const float*)d_in[7];
    const float* WK_w      = (const float*)d_in[8];
    const float* WK_b      = (const float*)d_in[9];
    float* out = (float*)d_out;

    // Projections: queries (Lx = L), concatenated keys (Lx = M)
    proj_kernel<<<dim3(Ld*Bd/64, Hd), 256>>>(rgbquery, rgbquery, Ld*Bd, Ld, WK_w, WK_b, 0);
    proj_kernel<<<dim3(Ld*Bd/64, Hd), 256>>>(tquery,   tquery,   Ld*Bd, Ld, WK_w, WK_b, 1);
    proj_kernel<<<dim3(Md*Bd/64, Hd), 256>>>(rgbkey,   fusekey,  Ld*Bd, Md, WK_w, WK_b, 2);
    proj_kernel<<<dim3(Md*Bd/64, Hd), 256>>>(tkey,     fusekey,  Ld*Bd, Md, WK_w, WK_b, 3);

    // Scores
    dot_kernel<<<dim3(Md/64, Ld/64, HBd), 256>>>(0);
    dot_kernel<<<dim3(Md/64, Ld/64, HBd), 256>>>(1);

    // Softmax stats
    stats_kernel<<<HBd*Ld, 256>>>();

    // Fused 4-way attend
    attend_kernel<<<dim3(Fd/64, Ld/64, HBd), 256>>>(rgbvalue, tvalue, fusevalue, out);
}

// round 2
// speedup vs baseline: 1.0452x; 1.0452x over previous
#include <cuda_runtime.h>
#include <math.h>

// Problem constants
#define Ld  1024
#define Bd  4
#define Fd  512
#define Hd  8
#define Kd  64
#define Md  2048          // Lk + Lfuse
#define HBd (Hd*Bd)       // 32
#define HFd (Hd*Fd)       // 4096

typedef unsigned long long ull;

// ---------------- scratch (device globals; no allocs allowed) ----------------
__device__ float g_RQ [HBd*Ld*Kd];             // (h*B+b, L, K)  8 MB
__device__ float g_TQ [HBd*Ld*Kd];
__device__ float g_FK [HBd*Md*Kd];             // (h*B+b, M, K) 16 MB
__device__ float g_FK1[HBd*Md*Kd];
__device__ float g_Srgb[(size_t)HBd*Ld*Md];    // raw dots -> then Pr (unnormalized exp)
__device__ float g_St  [(size_t)HBd*Ld*Md];    // raw dots -> then Pt
__device__ float g_Sx  [(size_t)HBd*Ld*Md];    // Px = exp(sr*st - m)
__device__ float g_stats[HBd*Ld*6];            // m_rgb,sum_rgb,m_t,sum_t,m_x,sum_x

// ---------------- packed f32x2 helpers (FFMA2 path, sm_103a) -----------------
__device__ __forceinline__ ull dupf(float x) {
    ull d; asm("mov.b64 %0, {%1, %1};" : "=l"(d) : "f"(x)); return d;
}
__device__ __forceinline__ void fma2(ull& d, ull a, ull b) {
    asm("fma.rn.f32x2 %0, %1, %2, %0;" : "+l"(d) : "l"(a), "l"(b));
}
__device__ __forceinline__ void unpack2(ull v, float& lo, float& hi) {
    asm("mov.b64 {%0, %1}, %2;" : "=f"(lo), "=f"(hi) : "l"(v));
}

// =====================================================================
// Kernel 1: projection + per-head L2 norm. (FFMA2 inner loop)
// grid: (Lx*B/64, H), block 256
// =====================================================================
__global__ __launch_bounds__(256)
void proj_kernel(const float* __restrict__ src0, const float* __restrict__ src1,
                 int rows0, int Lx,
                 const float* __restrict__ Wm, const float* __restrict__ bias,
                 int dst)
{
    __shared__ float Xs[32][68];
    __shared__ float Ws[32][68];
    float* out = (dst == 0) ? g_RQ : (dst == 1) ? g_TQ : (dst == 2) ? g_FK : g_FK1;

    const int h = blockIdx.y;
    const int rowBase = blockIdx.x * 64;
    const int tid = threadIdx.x;
    const int tx = tid & 15, ty = tid >> 4;

    ull A[2][4] = {};

    for (int k0 = 0; k0 < Fd; k0 += 32) {
        #pragma unroll
        for (int p = 0; p < 2; p++) {
            int id = tid + p * 256;         // 0..511
            int r  = id >> 3;               // 0..63
            int c4 = (id & 7) * 4;          // 0..28
            int gr = rowBase + r;
            const float* xr = (gr < rows0) ? (src0 + (size_t)gr * Fd)
                                           : (src1 + (size_t)(gr - rows0) * Fd);
            float4 v = *reinterpret_cast<const float4*>(xr + k0 + c4);
            Xs[c4+0][r] = v.x; Xs[c4+1][r] = v.y; Xs[c4+2][r] = v.z; Xs[c4+3][r] = v.w;
            float4 w = *reinterpret_cast<const float4*>(Wm + (size_t)(h*64 + r) * Fd + k0 + c4);
            Ws[c4+0][r] = w.x; Ws[c4+1][r] = w.y; Ws[c4+2][r] = w.z; Ws[c4+3][r] = w.w;
        }
        __syncthreads();
        #pragma unroll
        for (int kk = 0; kk < 32; kk++) {
            ulonglong2 x2 = *reinterpret_cast<const ulonglong2*>(&Xs[kk][ty*4]);
            float4 w = *reinterpret_cast<const float4*>(&Ws[kk][tx*4]);
            ull xp[2] = {x2.x, x2.y};
            ull wd[4] = {dupf(w.x), dupf(w.y), dupf(w.z), dupf(w.w)};
            #pragma unroll
            for (int p = 0; p < 2; p++)
                #pragma unroll
                for (int j = 0; j < 4; j++)
                    fma2(A[p][j], xp[p], wd[j]);
        }
        __syncthreads();
    }

    float acc[4][4];
    #pragma unroll
    for (int p = 0; p < 2; p++)
        #pragma unroll
        for (int j = 0; j < 4; j++)
            unpack2(A[p][j], acc[2*p][j], acc[2*p+1][j]);

    // bias (zeros per setup, but keep for fidelity)
    #pragma unroll
    for (int j = 0; j < 4; j++) {
        float bb = bias[h*64 + tx*4 + j];
        #pragma unroll
        for (int i = 0; i < 4; i++) acc[i][j] += bb;
    }

    // per-row L2 norm over the 64 head columns (reduce over 16 tx lanes)
    #pragma unroll
    for (int i = 0; i < 4; i++) {
        float s = 0.f;
        #pragma unroll
        for (int j = 0; j < 4; j++) s += acc[i][j] * acc[i][j];
        s += __shfl_xor_sync(0xffffffffu, s, 1);
        s += __shfl_xor_sync(0xffffffffu, s, 2);
        s += __shfl_xor_sync(0xffffffffu, s, 4);
        s += __shfl_xor_sync(0xffffffffu, s, 8);
        float inv = 1.0f / fmaxf(sqrtf(s), 1e-12f);
        int gr = rowBase + ty*4 + i;
        int l  = gr / Bd, b = gr % Bd;
        float4 o = make_float4(acc[i][0]*inv, acc[i][1]*inv, acc[i][2]*inv, acc[i][3]*inv);
        *reinterpret_cast<float4*>(out + ((size_t)(h*Bd + b) * Lx + l) * Kd + tx*4) = o;
    }
}

// =====================================================================
// Kernel 2: scores S[hb][l][m] = sum_k Q[hb][l][k]*Kn[hb][m][k]  (FFMA2)
// grid: (M/64, L/64, HB), block 256
// =====================================================================
__global__ __launch_bounds__(256)
void dot_kernel(int sel)
{
    __shared__ float Qs[64][68];
    __shared__ float Ks[64][68];
    const float* Qn = sel ? g_TQ  : g_RQ;
    const float* Kn = sel ? g_FK1 : g_FK;
    float*       S  = sel ? g_St  : g_Srgb;

    const int hb = blockIdx.z;
    const int mBase = blockIdx.x * 64, lBase = blockIdx.y * 64;
    const int tid = threadIdx.x;
    const int tx = tid & 15, ty = tid >> 4;
    const float* Qp = Qn + (size_t)hb * Ld * Kd;
    const float* Kp = Kn + (size_t)hb * Md * Kd;

    #pragma unroll
    for (int p = 0; p < 4; p++) {
        int id = tid + p * 256;        // 0..1023
        int r  = id >> 4;              // 0..63
        int c4 = (id & 15) * 4;        // 0..60
        float4 q = *reinterpret_cast<const float4*>(Qp + (size_t)(lBase + r) * Kd + c4);
        Qs[c4+0][r] = q.x; Qs[c4+1][r] = q.y; Qs[c4+2][r] = q.z; Qs[c4+3][r] = q.w;
        float4 k = *reinterpret_cast<const float4*>(Kp + (size_t)(mBase + r) * Kd + c4);
        Ks[c4+0][r] = k.x; Ks[c4+1][r] = k.y; Ks[c4+2][r] = k.z; Ks[c4+3][r] = k.w;
    }
    __syncthreads();

    ull A[2][4] = {};
    #pragma unroll 16
    for (int kk = 0; kk < 64; kk++) {
        ulonglong2 q2 = *reinterpret_cast<const ulonglong2*>(&Qs[kk][ty*4]);
        float4 k = *reinterpret_cast<const float4*>(&Ks[kk][tx*4]);
        ull qp[2] = {q2.x, q2.y};
        ull kd[4] = {dupf(k.x), dupf(k.y), dupf(k.z), dupf(k.w)};
        #pragma unroll
        for (int p = 0; p < 2; p++)
            #pragma unroll
            for (int j = 0; j < 4; j++)
                fma2(A[p][j], qp[p], kd[j]);
    }

    float acc[4][4];
    #pragma unroll
    for (int p = 0; p < 2; p++)
        #pragma unroll
        for (int j = 0; j < 4; j++)
            unpack2(A[p][j], acc[2*p][j], acc[2*p+1][j]);

    #pragma unroll
    for (int i = 0; i < 4; i++) {
        int l = lBase + ty*4 + i;
        float4 o = make_float4(acc[i][0], acc[i][1], acc[i][2], acc[i][3]);
        *reinterpret_cast<float4*>(S + ((size_t)hb * Ld + l) * Md + mBase + tx*4) = o;
    }
}

// =====================================================================
// Kernel 3: per-row softmax stats for the three affinities, AND
// materialize Pr/Pt/Px (unnormalized exp) into global, in place for
// g_Srgb/g_St and into g_Sx. Offloads all __expf from the attend kernel.
// grid: HB*L blocks of 256
// =====================================================================
__global__ __launch_bounds__(256)
void stats_kernel()
{
    const int row = blockIdx.x;
    float* sr = g_Srgb + (size_t)row * Md;
    float* st = g_St   + (size_t)row * Md;
    float* sx = g_Sx   + (size_t)row * Md;
    const int tid = threadIdx.x;
    const int lane = tid & 31, warp = tid >> 5;
    __shared__ float sm[8][6];

    float m1 = -1e30f, m2 = -1e30f, m3 = -1e30f;
    for (int i = tid; i < Md; i += 256) {
        float a = sr[i], b = st[i];
        m1 = fmaxf(m1, 100.f * a);
        m2 = fmaxf(m2, 100.f * b);
        m3 = fmaxf(m3, a * b);
    }
    #pragma unroll
    for (int o = 16; o > 0; o >>= 1) {
        m1 = fmaxf(m1, __shfl_xor_sync(0xffffffffu, m1, o));
        m2 = fmaxf(m2, __shfl_xor_sync(0xffffffffu, m2, o));
        m3 = fmaxf(m3, __shfl_xor_sync(0xffffffffu, m3, o));
    }
    if (lane == 0) { sm[warp][0] = m1; sm[warp][1] = m2; sm[warp][2] = m3; }
    __syncthreads();
    m1 = m2 = m3 = -1e30f;
    #pragma unroll
    for (int w = 0; w < 8; w++) {
        m1 = fmaxf(m1, sm[w][0]); m2 = fmaxf(m2, sm[w][1]); m3 = fmaxf(m3, sm[w][2]);
    }

    float s1 = 0.f, s2 = 0.f, s3 = 0.f;
    for (int i = tid; i < Md; i += 256) {
        float a = sr[i], b = st[i];
        float e1 = __expf(100.f * a - m1);
        float e2 = __expf(100.f * b - m2);
        float e3 = __expf(a * b - m3);
        s1 += e1; s2 += e2; s3 += e3;
        sr[i] = e1; st[i] = e2; sx[i] = e3;
    }
    #pragma unroll
    for (int o = 16; o > 0; o >>= 1) {
        s1 += __shfl_xor_sync(0xffffffffu, s1, o);
        s2 += __shfl_xor_sync(0xffffffffu, s2, o);
        s3 += __shfl_xor_sync(0xffffffffu, s3, o);
    }
    __syncthreads();
    if (lane == 0) { sm[warp][3] = s1; sm[warp][4] = s2; sm[warp][5] = s3; }
    __syncthreads();
    if (tid == 0) {
        s1 = s2 = s3 = 0.f;
        #pragma unroll
        for (int w = 0; w < 8; w++) { s1 += sm[w][3]; s2 += sm[w][4]; s3 += sm[w][5]; }
        float* o = g_stats + (size_t)row * 6;
        o[0] = m1; o[1] = s1; o[2] = m2; o[3] = s2; o[4] = m3; o[5] = s3;
    }
}

// =====================================================================
// Kernel 4: fused attend, FFMA2. Per (h,b, l-tile, f-tile): stream M in
// tiles of 32; P tiles loaded directly (exp precomputed). Four 64x64
// fp32 accumulations packed as f32x2 over the l-row-pair dimension.
// grid: (F/64, L/64, HB), block 256
// =====================================================================
__global__ __launch_bounds__(256, 2)
void attend_kernel(const float* __restrict__ rgbvalue,
                   const float* __restrict__ tvalue,
                   const float* __restrict__ fusevalue,
                   float* __restrict__ out)
{
    __shared__ float Pr[32][68], Pt[32][68], Px[32][68];
    __shared__ float Vr[32][68], Vt[32][68];

    const int hb = blockIdx.z;
    const int h  = hb / Bd, b = hb % Bd;
    const int fBase = blockIdx.x * 64, lBase = blockIdx.y * 64;
    const int tid = threadIdx.x;
    const int tx = tid & 15, ty = tid >> 4;

    const float* prp_g = g_Srgb + ((size_t)hb * Ld + lBase) * Md;
    const float* ptp_g = g_St   + ((size_t)hb * Ld + lBase) * Md;
    const float* pxp_g = g_Sx   + ((size_t)hb * Ld + lBase) * Md;

    ull A0[2][4] = {}, A1[2][4] = {}, A2[2][4] = {}, A3[2][4] = {};

    for (int m0 = 0; m0 < Md; m0 += 32) {
        // P tiles: rows 0..63 (l), cols m0..m0+31, stored transposed [m][l]
        #pragma unroll
        for (int p = 0; p < 2; p++) {
            int id = tid + p * 256;        // 0..511
            int r  = id >> 3;              // 0..63
            int c4 = (id & 7) * 4;
            float4 pa = *reinterpret_cast<const float4*>(prp_g + (size_t)r * Md + m0 + c4);
            float4 pb = *reinterpret_cast<const float4*>(ptp_g + (size_t)r * Md + m0 + c4);
            float4 pc = *reinterpret_cast<const float4*>(pxp_g + (size_t)r * Md + m0 + c4);
            Pr[c4+0][r] = pa.x; Pr[c4+1][r] = pa.y; Pr[c4+2][r] = pa.z; Pr[c4+3][r] = pa.w;
            Pt[c4+0][r] = pb.x; Pt[c4+1][r] = pb.y; Pt[c4+2][r] = pb.z; Pt[c4+3][r] = pb.w;
            Px[c4+0][r] = pc.x; Px[c4+1][r] = pc.y; Px[c4+2][r] = pc.z; Px[c4+3][r] = pc.w;
        }
        // V tiles: rows m0..m0+31 (m), cols fBase..fBase+63
        #pragma unroll
        for (int p = 0; p < 2; p++) {
            int id = tid + p * 256;        // 0..511
            int r  = id >> 4;              // 0..31
            int c4 = (id & 15) * 4;
            int m  = m0 + r;
            const float* vr = (m < Ld) ? rgbvalue + ((size_t)m * Bd + b) * Fd
                                       : fusevalue + ((size_t)(m - Ld) * Bd + b) * Fd;
            const float* vt = (m < Ld) ? tvalue   + ((size_t)m * Bd + b) * Fd
                                       : fusevalue + ((size_t)(m - Ld) * Bd + b) * Fd;
            *reinterpret_cast<float4*>(&Vr[r][c4]) = *reinterpret_cast<const float4*>(vr + fBase + c4);
            *reinterpret_cast<float4*>(&Vt[r][c4]) = *reinterpret_cast<const float4*>(vt + fBase + c4);
        }
        __syncthreads();

        #pragma unroll 8
        for (int kk = 0; kk < 32; kk++) {
            ulonglong2 pr2 = *reinterpret_cast<const ulonglong2*>(&Pr[kk][ty*4]);
            ulonglong2 pt2 = *reinterpret_cast<const ulonglong2*>(&Pt[kk][ty*4]);
            ulonglong2 px2 = *reinterpret_cast<const ulonglong2*>(&Px[kk][ty*4]);
            float4 vr = *reinterpret_cast<const float4*>(&Vr[kk][tx*4]);
            float4 vt = *reinterpret_cast<const float4*>(&Vt[kk][tx*4]);
            ull prp[2] = {pr2.x, pr2.y};
            ull ptp[2] = {pt2.x, pt2.y};
            ull pxp[2] = {px2.x, px2.y};
            ull vrd[4] = {dupf(vr.x), dupf(vr.y), dupf(vr.z), dupf(vr.w)};
            ull vtd[4] = {dupf(vt.x), dupf(vt.y), dupf(vt.z), dupf(vt.w)};
            #pragma unroll
            for (int p = 0; p < 2; p++)
                #pragma unroll
                for (int j = 0; j < 4; j++) {
                    fma2(A0[p][j], prp[p], vrd[j]);   // self_rgb
                    fma2(A1[p][j], ptp[p], vtd[j]);   // self_t
                    fma2(A2[p][j], pxp[p], vtd[j]);   // cross_rgb
                    fma2(A3[p][j], pxp[p], vrd[j]);   // cross_t
                }
        }
        __syncthreads();
    }

    float a0[4][4], a1[4][4], a2[4][4], a3[4][4];
    #pragma unroll
    for (int p = 0; p < 2; p++)
        #pragma unroll
        for (int j = 0; j < 4; j++) {
            unpack2(A0[p][j], a0[2*p][j], a0[2*p+1][j]);
            unpack2(A1[p][j], a1[2*p][j], a1[2*p+1][j]);
            unpack2(A2[p][j], a2[2*p][j], a2[2*p+1][j]);
            unpack2(A3[p][j], a3[2*p][j], a3[2*p+1][j]);
        }

    const size_t OSZ = (size_t)Ld * Bd * HFd;
    #pragma unroll
    for (int i = 0; i < 4; i++) {
        int l = lBase + ty*4 + i;
        const float* stw = g_stats + ((size_t)hb * Ld + l) * 6;
        float i1 = 1.f / stw[1], i2 = 1.f / stw[3], i3 = 1.f / stw[5];
        size_t base = ((size_t)l * Bd + b) * HFd + (size_t)h * Fd + fBase + tx*4;
        float4 o0 = make_float4(a0[i][0]*i1, a0[i][1]*i1, a0[i][2]*i1, a0[i][3]*i1);
        float4 o1 = make_float4(a1[i][0]*i2, a1[i][1]*i2, a1[i][2]*i2, a1[i][3]*i2);
        float4 o2 = make_float4(a2[i][0]*i3, a2[i][1]*i3, a2[i][2]*i3, a2[i][3]*i3);
        float4 o3 = make_float4(a3[i][0]*i3, a3[i][1]*i3, a3[i][2]*i3, a3[i][3]*i3);
        *reinterpret_cast<float4*>(out + 0*OSZ + base) = o0;
        *reinterpret_cast<float4*>(out + 1*OSZ + base) = o1;
        *reinterpret_cast<float4*>(out + 2*OSZ + base) = o2;
        *reinterpret_cast<float4*>(out + 3*OSZ + base) = o3;
    }
}

// =====================================================================
extern "C" void kernel_launch(void* const* d_in, const int* in_sizes, int n_in,
                              void* d_out, int out_size)
{
    const float* rgbquery  = (const float*)d_in[0];
    const float* rgbkey    = (const float*)d_in[1];
    const float* rgbvalue  = (const float*)d_in[2];
    const float* tquery    = (const float*)d_in[3];
    const float* tkey      = (const float*)d_in[4];
    const float* tvalue    = (const float*)d_in[5];
    const float* fusekey   = (const float*)d_in[6];
    const float* fusevalue = (const float*)d_in[7];
    const float* WK_w      = (const float*)d_in[8];
    const float* WK_b      = (const float*)d_in[9];
    float* out = (float*)d_out;

    // Projections: queries (Lx = L), concatenated keys (Lx = M)
    proj_kernel<<<dim3(Ld*Bd/64, Hd), 256>>>(rgbquery, rgbquery, Ld*Bd, Ld, WK_w, WK_b, 0);
    proj_kernel<<<dim3(Ld*Bd/64, Hd), 256>>>(tquery,   tquery,   Ld*Bd, Ld, WK_w, WK_b, 1);
    proj_kernel<<<dim3(Md*Bd/64, Hd), 256>>>(rgbkey,   fusekey,  Ld*Bd, Md, WK_w, WK_b, 2);
    proj_kernel<<<dim3(Md*Bd/64, Hd), 256>>>(tkey,     fusekey,  Ld*Bd, Md, WK_w, WK_b, 3);

    // Scores (raw dots)
    dot_kernel<<<dim3(Md/64, Ld/64, HBd), 256>>>(0);
    dot_kernel<<<dim3(Md/64, Ld/64, HBd), 256>>>(1);

    // Softmax stats + P materialization
    stats_kernel<<<HBd*Ld, 256>>>();

    // Fused 4-way attend (pure FFMA2 GEMM)
    attend_kernel<<<dim3(Fd/64, Ld/64, HBd), 256>>>(rgbvalue, tvalue, fusevalue, out);
}

// round 4
// speedup vs baseline: 2.0186x; 1.9314x over previous
#include <cuda_runtime.h>
#include <cstdint>
#include <math.h>

// Problem constants
#define Ld  1024
#define Bd  4
#define Fd  512
#define Hd  8
#define Kd  64
#define Md  2048          // Lk + Lfuse
#define HBd (Hd*Bd)       // 32
#define HFd (Hd*Fd)       // 4096

typedef unsigned long long ull;

// ---------------- scratch (device globals; no allocs allowed) ----------------
__device__ float g_RQ [HBd*Ld*Kd];
__device__ float g_TQ [HBd*Ld*Kd];
__device__ float g_FK [HBd*Md*Kd];
__device__ float g_FK1[HBd*Md*Kd];
__device__ float g_Srgb[(size_t)HBd*Ld*Md];    // raw dots -> Pr (unnormalized exp)
__device__ float g_St  [(size_t)HBd*Ld*Md];    // raw dots -> Pt
__device__ float g_Sx  [(size_t)HBd*Ld*Md];    // Px
__device__ float g_stats[HBd*Ld*6];

// ---------------- packed f32x2 helpers -----------------
__device__ __forceinline__ ull dupf(float x) {
    ull d; asm("mov.b64 %0, {%1, %1};" : "=l"(d) : "f"(x)); return d;
}
__device__ __forceinline__ void fma2(ull& d, ull a, ull b) {
    asm("fma.rn.f32x2 %0, %1, %2, %0;" : "+l"(d) : "l"(a), "l"(b));
}
__device__ __forceinline__ void unpack2(ull v, float& lo, float& hi) {
    asm("mov.b64 {%0, %1}, %2;" : "=f"(lo), "=f"(hi) : "l"(v));
}

// ---------------- tf32 mma.sync helpers (baseline PTX, works on sm_103) ------
__device__ __forceinline__ float to_tf32(float x) {
    float y; asm("cvt.rna.tf32.f32 %0, %1;" : "=f"(y) : "f"(x)); return y;
}
__device__ __forceinline__ void mma_tf32(float* c,
                                         uint32_t a0, uint32_t a1, uint32_t a2, uint32_t a3,
                                         uint32_t b0, uint32_t b1) {
    asm volatile(
        "mma.sync.aligned.m16n8k8.row.col.f32.tf32.tf32.f32 "
        "{%0,%1,%2,%3}, {%4,%5,%6,%7}, {%8,%9}, {%0,%1,%2,%3};"
        : "+f"(c[0]), "+f"(c[1]), "+f"(c[2]), "+f"(c[3])
        : "r"(a0), "r"(a1), "r"(a2), "r"(a3), "r"(b0), "r"(b1));
}

// =====================================================================
// Kernel 1: projection + per-head L2 norm. (unchanged, passing)
// =====================================================================
__global__ __launch_bounds__(256)
void proj_kernel(const float* __restrict__ src0, const float* __restrict__ src1,
                 int rows0, int Lx,
                 const float* __restrict__ Wm, const float* __restrict__ bias,
                 int dst)
{
    __shared__ float Xs[32][68];
    __shared__ float Ws[32][68];
    float* out = (dst == 0) ? g_RQ : (dst == 1) ? g_TQ : (dst == 2) ? g_FK : g_FK1;

    const int h = blockIdx.y;
    const int rowBase = blockIdx.x * 64;
    const int tid = threadIdx.x;
    const int tx = tid & 15, ty = tid >> 4;

    ull A[2][4] = {};

    for (int k0 = 0; k0 < Fd; k0 += 32) {
        #pragma unroll
        for (int p = 0; p < 2; p++) {
            int id = tid + p * 256;
            int r  = id >> 3;
            int c4 = (id & 7) * 4;
            int gr = rowBase + r;
            const float* xr = (gr < rows0) ? (src0 + (size_t)gr * Fd)
                                           : (src1 + (size_t)(gr - rows0) * Fd);
            float4 v = *reinterpret_cast<const float4*>(xr + k0 + c4);
            Xs[c4+0][r] = v.x; Xs[c4+1][r] = v.y; Xs[c4+2][r] = v.z; Xs[c4+3][r] = v.w;
            float4 w = *reinterpret_cast<const float4*>(Wm + (size_t)(h*64 + r) * Fd + k0 + c4);
            Ws[c4+0][r] = w.x; Ws[c4+1][r] = w.y; Ws[c4+2][r] = w.z; Ws[c4+3][r] = w.w;
        }
        __syncthreads();
        #pragma unroll
        for (int kk = 0; kk < 32; kk++) {
            ulonglong2 x2 = *reinterpret_cast<const ulonglong2*>(&Xs[kk][ty*4]);
            float4 w = *reinterpret_cast<const float4*>(&Ws[kk][tx*4]);
            ull xp[2] = {x2.x, x2.y};
            ull wd[4] = {dupf(w.x), dupf(w.y), dupf(w.z), dupf(w.w)};
            #pragma unroll
            for (int p = 0; p < 2; p++)
                #pragma unroll
                for (int j = 0; j < 4; j++)
                    fma2(A[p][j], xp[p], wd[j]);
        }
        __syncthreads();
    }

    float acc[4][4];
    #pragma unroll
    for (int p = 0; p < 2; p++)
        #pragma unroll
        for (int j = 0; j < 4; j++)
            unpack2(A[p][j], acc[2*p][j], acc[2*p+1][j]);

    #pragma unroll
    for (int j = 0; j < 4; j++) {
        float bb = bias[h*64 + tx*4 + j];
        #pragma unroll
        for (int i = 0; i < 4; i++) acc[i][j] += bb;
    }

    #pragma unroll
    for (int i = 0; i < 4; i++) {
        float s = 0.f;
        #pragma unroll
        for (int j = 0; j < 4; j++) s += acc[i][j] * acc[i][j];
        s += __shfl_xor_sync(0xffffffffu, s, 1);
        s += __shfl_xor_sync(0xffffffffu, s, 2);
        s += __shfl_xor_sync(0xffffffffu, s, 4);
        s += __shfl_xor_sync(0xffffffffu, s, 8);
        float inv = 1.0f / fmaxf(sqrtf(s), 1e-12f);
        int gr = rowBase + ty*4 + i;
        int l  = gr / Bd, b = gr % Bd;
        float4 o = make_float4(acc[i][0]*inv, acc[i][1]*inv, acc[i][2]*inv, acc[i][3]*inv);
        *reinterpret_cast<float4*>(out + ((size_t)(h*Bd + b) * Lx + l) * Kd + tx*4) = o;
    }
}

// =====================================================================
// Kernel 2: scores (fp32 — logits need full precision). Unchanged.
// =====================================================================
__global__ __launch_bounds__(256)
void dot_kernel(int sel)
{
    __shared__ float Qs[64][68];
    __shared__ float Ks[64][68];
    const float* Qn = sel ? g_TQ  : g_RQ;
    const float* Kn = sel ? g_FK1 : g_FK;
    float*       S  = sel ? g_St  : g_Srgb;

    const int hb = blockIdx.z;
    const int mBase = blockIdx.x * 64, lBase = blockIdx.y * 64;
    const int tid = threadIdx.x;
    const int tx = tid & 15, ty = tid >> 4;
    const float* Qp = Qn + (size_t)hb * Ld * Kd;
    const float* Kp = Kn + (size_t)hb * Md * Kd;

    #pragma unroll
    for (int p = 0; p < 4; p++) {
        int id = tid + p * 256;
        int r  = id >> 4;
        int c4 = (id & 15) * 4;
        float4 q = *reinterpret_cast<const float4*>(Qp + (size_t)(lBase + r) * Kd + c4);
        Qs[c4+0][r] = q.x; Qs[c4+1][r] = q.y; Qs[c4+2][r] = q.z; Qs[c4+3][r] = q.w;
        float4 k = *reinterpret_cast<const float4*>(Kp + (size_t)(mBase + r) * Kd + c4);
        Ks[c4+0][r] = k.x; Ks[c4+1][r] = k.y; Ks[c4+2][r] = k.z; Ks[c4+3][r] = k.w;
    }
    __syncthreads();

    ull A[2][4] = {};
    #pragma unroll 16
    for (int kk = 0; kk < 64; kk++) {
        ulonglong2 q2 = *reinterpret_cast<const ulonglong2*>(&Qs[kk][ty*4]);
        float4 k = *reinterpret_cast<const float4*>(&Ks[kk][tx*4]);
        ull qp[2] = {q2.x, q2.y};
        ull kd[4] = {dupf(k.x), dupf(k.y), dupf(k.z), dupf(k.w)};
        #pragma unroll
        for (int p = 0; p < 2; p++)
            #pragma unroll
            for (int j = 0; j < 4; j++)
                fma2(A[p][j], qp[p], kd[j]);
    }

    float acc[4][4];
    #pragma unroll
    for (int p = 0; p < 2; p++)
        #pragma unroll
        for (int j = 0; j < 4; j++)
            unpack2(A[p][j], acc[2*p][j], acc[2*p+1][j]);

    #pragma unroll
    for (int i = 0; i < 4; i++) {
        int l = lBase + ty*4 + i;
        float4 o = make_float4(acc[i][0], acc[i][1], acc[i][2], acc[i][3]);
        *reinterpret_cast<float4*>(S + ((size_t)hb * Ld + l) * Md + mBase + tx*4) = o;
    }
}

// =====================================================================
// Kernel 3: softmax stats + P materialization. Unchanged.
// =====================================================================
__global__ __launch_bounds__(256)
void stats_kernel()
{
    const int row = blockIdx.x;
    float* sr = g_Srgb + (size_t)row * Md;
    float* st = g_St   + (size_t)row * Md;
    float* sx = g_Sx   + (size_t)row * Md;
    const int tid = threadIdx.x;
    const int lane = tid & 31, warp = tid >> 5;
    __shared__ float sm[8][6];

    float m1 = -1e30f, m2 = -1e30f, m3 = -1e30f;
    for (int i = tid; i < Md; i += 256) {
        float a = sr[i], b = st[i];
        m1 = fmaxf(m1, 100.f * a);
        m2 = fmaxf(m2, 100.f * b);
        m3 = fmaxf(m3, a * b);
    }
    #pragma unroll
    for (int o = 16; o > 0; o >>= 1) {
        m1 = fmaxf(m1, __shfl_xor_sync(0xffffffffu, m1, o));
        m2 = fmaxf(m2, __shfl_xor_sync(0xffffffffu, m2, o));
        m3 = fmaxf(m3, __shfl_xor_sync(0xffffffffu, m3, o));
    }
    if (lane == 0) { sm[warp][0] = m1; sm[warp][1] = m2; sm[warp][2] = m3; }
    __syncthreads();
    m1 = m2 = m3 = -1e30f;
    #pragma unroll
    for (int w = 0; w < 8; w++) {
        m1 = fmaxf(m1, sm[w][0]); m2 = fmaxf(m2, sm[w][1]); m3 = fmaxf(m3, sm[w][2]);
    }

    float s1 = 0.f, s2 = 0.f, s3 = 0.f;
    for (int i = tid; i < Md; i += 256) {
        float a = sr[i], b = st[i];
        float e1 = __expf(100.f * a - m1);
        float e2 = __expf(100.f * b - m2);
        float e3 = __expf(a * b - m3);
        s1 += e1; s2 += e2; s3 += e3;
        sr[i] = e1; st[i] = e2; sx[i] = e3;
    }
    #pragma unroll
    for (int o = 16; o > 0; o >>= 1) {
        s1 += __shfl_xor_sync(0xffffffffu, s1, o);
        s2 += __shfl_xor_sync(0xffffffffu, s2, o);
        s3 += __shfl_xor_sync(0xffffffffu, s3, o);
    }
    __syncthreads();
    if (lane == 0) { sm[warp][3] = s1; sm[warp][4] = s2; sm[warp][5] = s3; }
    __syncthreads();
    if (tid == 0) {
        s1 = s2 = s3 = 0.f;
        #pragma unroll
        for (int w = 0; w < 8; w++) { s1 += sm[w][3]; s2 += sm[w][4]; s3 += sm[w][5]; }
        float* o = g_stats + (size_t)row * 6;
        o[0] = m1; o[1] = s1; o[2] = m2; o[3] = s2; o[4] = m3; o[5] = s3;
    }
}

// =====================================================================
// Kernel 4: attend via mma.sync tf32 (tensor pipe, baseline PTX).
// Block tile 64(l) x 64(f); 8 warps, each 16(l) x 32(f).
// Stream m in chunks of 32 = 4 K-steps of 8.
// A = P[l][m] (pad 36, conflict-free), B = V[m][f] (pad 72, conflict-free).
// Both rounded to tf32 at SMEM-store time.
// grid: (F/64, L/64, HB), block 256
// =====================================================================
__global__ __launch_bounds__(256, 2)
void attend_mma_kernel(const float* __restrict__ rgbvalue,
                       const float* __restrict__ tvalue,
                       const float* __restrict__ fusevalue,
                       float* __restrict__ out)
{
    __shared__ float Pr[64][36], Pt[64][36], Px[64][36];
    __shared__ float Vr[32][72], Vt[32][72];

    const int hb = blockIdx.z;
    const int h  = hb / Bd, b = hb % Bd;
    const int fBase = blockIdx.x * 64, lBase = blockIdx.y * 64;
    const int tid = threadIdx.x;
    const int wid = tid >> 5, lane = tid & 31;
    const int wl = wid & 3;           // l group: 16 rows
    const int wf = wid >> 2;          // f group: 32 cols
    const int r = lane >> 2, c = lane & 3;

    const float* prp_g = g_Srgb + ((size_t)hb * Ld + lBase) * Md;
    const float* ptp_g = g_St   + ((size_t)hb * Ld + lBase) * Md;
    const float* pxp_g = g_Sx   + ((size_t)hb * Ld + lBase) * Md;

    // acc[out][ntile][reg] : out0=self_rgb(Pr,Vr) out1=self_t(Pt,Vt)
    //                        out2=cross_rgb(Px,Vt) out3=cross_t(Px,Vr)
    float acc[4][4][4] = {};

    for (int m0 = 0; m0 < Md; m0 += 32) {
        // ---- P tiles: [l 0..63][m 0..31], row-major, tf32-rounded ----
        #pragma unroll
        for (int p = 0; p < 2; p++) {
            int id = tid + p * 256;          // 0..511
            int rr = id >> 3;                // 0..63
            int c4 = (id & 7) * 4;           // 0..28
            float4 pa = *reinterpret_cast<const float4*>(prp_g + (size_t)rr * Md + m0 + c4);
            float4 pb = *reinterpret_cast<const float4*>(ptp_g + (size_t)rr * Md + m0 + c4);
            float4 pc = *reinterpret_cast<const float4*>(pxp_g + (size_t)rr * Md + m0 + c4);
            Pr[rr][c4+0] = to_tf32(pa.x); Pr[rr][c4+1] = to_tf32(pa.y);
            Pr[rr][c4+2] = to_tf32(pa.z); Pr[rr][c4+3] = to_tf32(pa.w);
            Pt[rr][c4+0] = to_tf32(pb.x); Pt[rr][c4+1] = to_tf32(pb.y);
            Pt[rr][c4+2] = to_tf32(pb.z); Pt[rr][c4+3] = to_tf32(pb.w);
            Px[rr][c4+0] = to_tf32(pc.x); Px[rr][c4+1] = to_tf32(pc.y);
            Px[rr][c4+2] = to_tf32(pc.z); Px[rr][c4+3] = to_tf32(pc.w);
        }
        // ---- V tiles: [m 0..31][f 0..63], tf32-rounded ----
        #pragma unroll
        for (int p = 0; p < 2; p++) {
            int id = tid + p * 256;          // 0..511
            int m  = id >> 4;                // 0..31
            int f4 = (id & 15) * 4;          // 0..60
            int mm = m0 + m;
            const float* vr = (mm < Ld) ? rgbvalue + ((size_t)mm * Bd + b) * Fd
                                        : fusevalue + ((size_t)(mm - Ld) * Bd + b) * Fd;
            const float* vt = (mm < Ld) ? tvalue   + ((size_t)mm * Bd + b) * Fd
                                        : fusevalue + ((size_t)(mm - Ld) * Bd + b) * Fd;
            float4 a  = *reinterpret_cast<const float4*>(vr + fBase + f4);
            float4 bb = *reinterpret_cast<const float4*>(vt + fBase + f4);
            Vr[m][f4+0] = to_tf32(a.x);  Vr[m][f4+1] = to_tf32(a.y);
            Vr[m][f4+2] = to_tf32(a.z);  Vr[m][f4+3] = to_tf32(a.w);
            Vt[m][f4+0] = to_tf32(bb.x); Vt[m][f4+1] = to_tf32(bb.y);
            Vt[m][f4+2] = to_tf32(bb.z); Vt[m][f4+3] = to_tf32(bb.w);
        }
        __syncthreads();

        #pragma unroll
        for (int ks = 0; ks < 4; ks++) {
            const int k0 = ks * 8;
            const int la = wl * 16 + r;
            // A fragments (m16k8): (r,c),(r+8,c),(r,c+4),(r+8,c+4)
            uint32_t ar0 = __float_as_uint(Pr[la  ][k0+c]);
            uint32_t ar1 = __float_as_uint(Pr[la+8][k0+c]);
            uint32_t ar2 = __float_as_uint(Pr[la  ][k0+c+4]);
            uint32_t ar3 = __float_as_uint(Pr[la+8][k0+c+4]);
            uint32_t at0 = __float_as_uint(Pt[la  ][k0+c]);
            uint32_t at1 = __float_as_uint(Pt[la+8][k0+c]);
            uint32_t at2 = __float_as_uint(Pt[la  ][k0+c+4]);
            uint32_t at3 = __float_as_uint(Pt[la+8][k0+c+4]);
            uint32_t ax0 = __float_as_uint(Px[la  ][k0+c]);
            uint32_t ax1 = __float_as_uint(Px[la+8][k0+c]);
            uint32_t ax2 = __float_as_uint(Px[la  ][k0+c+4]);
            uint32_t ax3 = __float_as_uint(Px[la+8][k0+c+4]);
            #pragma unroll
            for (int nt = 0; nt < 4; nt++) {
                const int fc = wf * 32 + nt * 8 + r;   // B col n = lane>>2
                // B fragments (k8n8 col-major): b0=(k=c,n), b1=(k=c+4,n)
                uint32_t br0 = __float_as_uint(Vr[k0+c  ][fc]);
                uint32_t br1 = __float_as_uint(Vr[k0+c+4][fc]);
                uint32_t bt0 = __float_as_uint(Vt[k0+c  ][fc]);
                uint32_t bt1 = __float_as_uint(Vt[k0+c+4][fc]);
                mma_tf32(acc[0][nt], ar0, ar1, ar2, ar3, br0, br1);
                mma_tf32(acc[1][nt], at0, at1, at2, at3, bt0, bt1);
                mma_tf32(acc[2][nt], ax0, ax1, ax2, ax3, bt0, bt1);
                mma_tf32(acc[3][nt], ax0, ax1, ax2, ax3, br0, br1);
            }
        }
        __syncthreads();
    }

    // ---- Epilogue: scale by 1/sum, write float2 per (out, ntile, row-half) ----
    const size_t OSZ = (size_t)Ld * Bd * HFd;
    const int l0 = lBase + wl * 16 + r;
    const int l1 = l0 + 8;
    const float* st0 = g_stats + ((size_t)hb * Ld + l0) * 6;
    const float* st1 = g_stats + ((size_t)hb * Ld + l1) * 6;
    const float inv0[4] = {1.f/st0[1], 1.f/st0[3], 1.f/st0[5], 1.f/st0[5]};
    const float inv1[4] = {1.f/st1[1], 1.f/st1[3], 1.f/st1[5], 1.f/st1[5]};
    const size_t base0 = ((size_t)l0 * Bd + b) * HFd + (size_t)h * Fd;
    const size_t base1 = ((size_t)l1 * Bd + b) * HFd + (size_t)h * Fd;
    #pragma unroll
    for (int d = 0; d < 4; d++) {
        #pragma unroll
        for (int nt = 0; nt < 4; nt++) {
            int f = fBase + wf * 32 + nt * 8 + 2 * c;
            float2 o0 = make_float2(acc[d][nt][0] * inv0[d], acc[d][nt][1] * inv0[d]);
            float2 o1 = make_float2(acc[d][nt][2] * inv1[d], acc[d][nt][3] * inv1[d]);
            *reinterpret_cast<float2*>(out + d*OSZ + base0 + f) = o0;
            *reinterpret_cast<float2*>(out + d*OSZ + base1 + f) = o1;
        }
    }
}

// =====================================================================
extern "C" void kernel_launch(void* const* d_in, const int* in_sizes, int n_in,
                              void* d_out, int out_size)
{
    const float* rgbquery  = (const float*)d_in[0];
    const float* rgbkey    = (const float*)d_in[1];
    const float* rgbvalue  = (const float*)d_in[2];
    const float* tquery    = (const float*)d_in[3];
    const float* tkey      = (const float*)d_in[4];
    const float* tvalue    = (const float*)d_in[5];
    const float* fusekey   = (const float*)d_in[6];
    const float* fusevalue = (const float*)d_in[7];
    const float* WK_w      = (const float*)d_in[8];
    const float* WK_b      = (const float*)d_in[9];
    float* out = (float*)d_out;

    proj_kernel<<<dim3(Ld*Bd/64, Hd), 256>>>(rgbquery, rgbquery, Ld*Bd, Ld, WK_w, WK_b, 0);
    proj_kernel<<<dim3(Ld*Bd/64, Hd), 256>>>(tquery,   tquery,   Ld*Bd, Ld, WK_w, WK_b, 1);
    proj_kernel<<<dim3(Md*Bd/64, Hd), 256>>>(rgbkey,   fusekey,  Ld*Bd, Md, WK_w, WK_b, 2);
    proj_kernel<<<dim3(Md*Bd/64, Hd), 256>>>(tkey,     fusekey,  Ld*Bd, Md, WK_w, WK_b, 3);

    dot_kernel<<<dim3(Md/64, Ld/64, HBd), 256>>>(0);
    dot_kernel<<<dim3(Md/64, Ld/64, HBd), 256>>>(1);

    stats_kernel<<<HBd*Ld, 256>>>();

    attend_mma_kernel<<<dim3(Fd/64, Ld/64, HBd), 256>>>(rgbvalue, tvalue, fusevalue, out);
}

// round 5
// speedup vs baseline: 2.0952x; 1.0380x over previous
#include <cuda_runtime.h>
#include <cuda_fp16.h>
#include <cstdint>
#include <math.h>

// Problem constants
#define Ld  1024
#define Bd  4
#define Fd  512
#define Hd  8
#define Kd  64
#define Md  2048          // Lk + Lfuse
#define HBd (Hd*Bd)       // 32
#define HFd (Hd*Fd)       // 4096

typedef unsigned long long ull;

// ---------------- scratch (device globals; no allocs allowed) ----------------
__device__ float  g_RQ [HBd*Ld*Kd];
__device__ float  g_TQ [HBd*Ld*Kd];
__device__ float  g_FK [HBd*Md*Kd];
__device__ float  g_FK1[HBd*Md*Kd];
__device__ float  g_Srgb[(size_t)HBd*Ld*Md];    // raw dots (fp32)
__device__ float  g_St  [(size_t)HBd*Ld*Md];    // raw dots (fp32)
__device__ __half g_PrH[(size_t)HBd*Ld*Md];     // exp(100*sr - m1) as half
__device__ __half g_PtH[(size_t)HBd*Ld*Md];     // exp(100*st - m2)
__device__ __half g_PxH[(size_t)HBd*Ld*Md];     // exp(sr*st - m3)
__device__ float  g_stats[HBd*Ld*6];

// ---------------- packed f32x2 helpers -----------------
__device__ __forceinline__ ull dupf(float x) {
    ull d; asm("mov.b64 %0, {%1, %1};" : "=l"(d) : "f"(x)); return d;
}
__device__ __forceinline__ void fma2(ull& d, ull a, ull b) {
    asm("fma.rn.f32x2 %0, %1, %2, %0;" : "+l"(d) : "l"(a), "l"(b));
}
__device__ __forceinline__ void unpack2(ull v, float& lo, float& hi) {
    asm("mov.b64 {%0, %1}, %2;" : "=f"(lo), "=f"(hi) : "l"(v));
}

// ---------------- fp16 mma.sync helper (baseline PTX) ------
__device__ __forceinline__ void mma_f16(float* c,
                                        uint32_t a0, uint32_t a1, uint32_t a2, uint32_t a3,
                                        uint32_t b0, uint32_t b1) {
    asm volatile(
        "mma.sync.aligned.m16n8k16.row.col.f32.f16.f16.f32 "
        "{%0,%1,%2,%3}, {%4,%5,%6,%7}, {%8,%9}, {%0,%1,%2,%3};"
        : "+f"(c[0]), "+f"(c[1]), "+f"(c[2]), "+f"(c[3])
        : "r"(a0), "r"(a1), "r"(a2), "r"(a3), "r"(b0), "r"(b1));
}

// =====================================================================
// Kernel 1: ALL FOUR projections in one launch (overlap latency).
// grid: (384, 8): bx<64 -> rgbquery, <128 -> tquery, <256 -> rgb keys,
// else t keys. Keys concatenate {key, fusekey} along rows.
// =====================================================================
__global__ __launch_bounds__(256)
void proj_kernel(const float* __restrict__ rgbquery, const float* __restrict__ tquery,
                 const float* __restrict__ rgbkey,   const float* __restrict__ tkey,
                 const float* __restrict__ fusekey,
                 const float* __restrict__ Wm, const float* __restrict__ bias)
{
    __shared__ float Xs[32][68];
    __shared__ float Ws[32][68];

    const int bx = blockIdx.x;
    const float *src0, *src1;
    float* out;
    int rowBase, Lx;
    if (bx < 64)       { src0 = rgbquery; src1 = rgbquery; out = g_RQ;  rowBase = bx * 64;        Lx = Ld; }
    else if (bx < 128) { src0 = tquery;   src1 = tquery;   out = g_TQ;  rowBase = (bx-64) * 64;   Lx = Ld; }
    else if (bx < 256) { src0 = rgbkey;   src1 = fusekey;  out = g_FK;  rowBase = (bx-128) * 64;  Lx = Md; }
    else               { src0 = tkey;     src1 = fusekey;  out = g_FK1; rowBase = (bx-256) * 64;  Lx = Md; }
    const int rows0 = Ld * Bd;

    const int h = blockIdx.y;
    const int tid = threadIdx.x;
    const int tx = tid & 15, ty = tid >> 4;

    ull A[2][4] = {};

    for (int k0 = 0; k0 < Fd; k0 += 32) {
        #pragma unroll
        for (int p = 0; p < 2; p++) {
            int id = tid + p * 256;
            int r  = id >> 3;
            int c4 = (id & 7) * 4;
            int gr = rowBase + r;
            const float* xr = (gr < rows0) ? (src0 + (size_t)gr * Fd)
                                           : (src1 + (size_t)(gr - rows0) * Fd);
            float4 v = *reinterpret_cast<const float4*>(xr + k0 + c4);
            Xs[c4+0][r] = v.x; Xs[c4+1][r] = v.y; Xs[c4+2][r] = v.z; Xs[c4+3][r] = v.w;
            float4 w = *reinterpret_cast<const float4*>(Wm + (size_t)(h*64 + r) * Fd + k0 + c4);
            Ws[c4+0][r] = w.x; Ws[c4+1][r] = w.y; Ws[c4+2][r] = w.z; Ws[c4+3][r] = w.w;
        }
        __syncthreads();
        #pragma unroll
        for (int kk = 0; kk < 32; kk++) {
            ulonglong2 x2 = *reinterpret_cast<const ulonglong2*>(&Xs[kk][ty*4]);
            float4 w = *reinterpret_cast<const float4*>(&Ws[kk][tx*4]);
            ull xp[2] = {x2.x, x2.y};
            ull wd[4] = {dupf(w.x), dupf(w.y), dupf(w.z), dupf(w.w)};
            #pragma unroll
            for (int p = 0; p < 2; p++)
                #pragma unroll
                for (int j = 0; j < 4; j++)
                    fma2(A[p][j], xp[p], wd[j]);
        }
        __syncthreads();
    }

    float acc[4][4];
    #pragma unroll
    for (int p = 0; p < 2; p++)
        #pragma unroll
        for (int j = 0; j < 4; j++)
            unpack2(A[p][j], acc[2*p][j], acc[2*p+1][j]);

    #pragma unroll
    for (int j = 0; j < 4; j++) {
        float bb = bias[h*64 + tx*4 + j];
        #pragma unroll
        for (int i = 0; i < 4; i++) acc[i][j] += bb;
    }

    #pragma unroll
    for (int i = 0; i < 4; i++) {
        float s = 0.f;
        #pragma unroll
        for (int j = 0; j < 4; j++) s += acc[i][j] * acc[i][j];
        s += __shfl_xor_sync(0xffffffffu, s, 1);
        s += __shfl_xor_sync(0xffffffffu, s, 2);
        s += __shfl_xor_sync(0xffffffffu, s, 4);
        s += __shfl_xor_sync(0xffffffffu, s, 8);
        float inv = 1.0f / fmaxf(sqrtf(s), 1e-12f);
        int gr = rowBase + ty*4 + i;
        int l  = gr / Bd, b = gr % Bd;
        *reinterpret_cast<float4*>(out + ((size_t)(h*Bd + b) * Lx + l) * Kd + tx*4) =
            make_float4(acc[i][0]*inv, acc[i][1]*inv, acc[i][2]*inv, acc[i][3]*inv);
    }
}

// =====================================================================
// Kernel 2: both score GEMMs in one launch. grid: (M/64, L/64, 2*HB)
// =====================================================================
__global__ __launch_bounds__(256)
void dot_kernel()
{
    __shared__ float Qs[64][68];
    __shared__ float Ks[64][68];
    const int hb2 = blockIdx.z;
    const int sel = hb2 / HBd;
    const int hb  = hb2 % HBd;
    const float* Qn = sel ? g_TQ  : g_RQ;
    const float* Kn = sel ? g_FK1 : g_FK;
    float*       S  = sel ? g_St  : g_Srgb;

    const int mBase = blockIdx.x * 64, lBase = blockIdx.y * 64;
    const int tid = threadIdx.x;
    const int tx = tid & 15, ty = tid >> 4;
    const float* Qp = Qn + (size_t)hb * Ld * Kd;
    const float* Kp = Kn + (size_t)hb * Md * Kd;

    #pragma unroll
    for (int p = 0; p < 4; p++) {
        int id = tid + p * 256;
        int r  = id >> 4;
        int c4 = (id & 15) * 4;
        float4 q = *reinterpret_cast<const float4*>(Qp + (size_t)(lBase + r) * Kd + c4);
        Qs[c4+0][r] = q.x; Qs[c4+1][r] = q.y; Qs[c4+2][r] = q.z; Qs[c4+3][r] = q.w;
        float4 k = *reinterpret_cast<const float4*>(Kp + (size_t)(mBase + r) * Kd + c4);
        Ks[c4+0][r] = k.x; Ks[c4+1][r] = k.y; Ks[c4+2][r] = k.z; Ks[c4+3][r] = k.w;
    }
    __syncthreads();

    ull A[2][4] = {};
    #pragma unroll 16
    for (int kk = 0; kk < 64; kk++) {
        ulonglong2 q2 = *reinterpret_cast<const ulonglong2*>(&Qs[kk][ty*4]);
        float4 k = *reinterpret_cast<const float4*>(&Ks[kk][tx*4]);
        ull qp[2] = {q2.x, q2.y};
        ull kd[4] = {dupf(k.x), dupf(k.y), dupf(k.z), dupf(k.w)};
        #pragma unroll
        for (int p = 0; p < 2; p++)
            #pragma unroll
            for (int j = 0; j < 4; j++)
                fma2(A[p][j], qp[p], kd[j]);
    }

    float acc[4][4];
    #pragma unroll
    for (int p = 0; p < 2; p++)
        #pragma unroll
        for (int j = 0; j < 4; j++)
            unpack2(A[p][j], acc[2*p][j], acc[2*p+1][j]);

    #pragma unroll
    for (int i = 0; i < 4; i++) {
        int l = lBase + ty*4 + i;
        *reinterpret_cast<float4*>(S + ((size_t)hb * Ld + l) * Md + mBase + tx*4) =
            make_float4(acc[i][0], acc[i][1], acc[i][2], acc[i][3]);
    }
}

// =====================================================================
// Kernel 3: softmax stats + P materialization as fp16. float4 passes.
// =====================================================================
__global__ __launch_bounds__(256)
void stats_kernel()
{
    const int row = blockIdx.x;
    const float* sr = g_Srgb + (size_t)row * Md;
    const float* st = g_St   + (size_t)row * Md;
    __half* pr = g_PrH + (size_t)row * Md;
    __half* pt = g_PtH + (size_t)row * Md;
    __half* px = g_PxH + (size_t)row * Md;
    const int tid = threadIdx.x;
    const int lane = tid & 31, warp = tid >> 5;
    __shared__ float sm[8][6];

    float m1 = -1e30f, m2 = -1e30f, m3 = -1e30f;
    #pragma unroll
    for (int it = 0; it < 2; it++) {
        int i = (tid + it * 256) * 4;
        float4 a = *reinterpret_cast<const float4*>(sr + i);
        float4 b = *reinterpret_cast<const float4*>(st + i);
        m1 = fmaxf(m1, fmaxf(fmaxf(a.x, a.y), fmaxf(a.z, a.w)));
        m2 = fmaxf(m2, fmaxf(fmaxf(b.x, b.y), fmaxf(b.z, b.w)));
        m3 = fmaxf(m3, fmaxf(fmaxf(a.x*b.x, a.y*b.y), fmaxf(a.z*b.z, a.w*b.w)));
    }
    m1 *= 100.f; m2 *= 100.f;   // max(100*x) == 100*max(x)
    #pragma unroll
    for (int o = 16; o > 0; o >>= 1) {
        m1 = fmaxf(m1, __shfl_xor_sync(0xffffffffu, m1, o));
        m2 = fmaxf(m2, __shfl_xor_sync(0xffffffffu, m2, o));
        m3 = fmaxf(m3, __shfl_xor_sync(0xffffffffu, m3, o));
    }
    if (lane == 0) { sm[warp][0] = m1; sm[warp][1] = m2; sm[warp][2] = m3; }
    __syncthreads();
    m1 = m2 = m3 = -1e30f;
    #pragma unroll
    for (int w = 0; w < 8; w++) {
        m1 = fmaxf(m1, sm[w][0]); m2 = fmaxf(m2, sm[w][1]); m3 = fmaxf(m3, sm[w][2]);
    }

    float s1 = 0.f, s2 = 0.f, s3 = 0.f;
    #pragma unroll
    for (int it = 0; it < 2; it++) {
        int i = (tid + it * 256) * 4;
        float4 a = *reinterpret_cast<const float4*>(sr + i);
        float4 b = *reinterpret_cast<const float4*>(st + i);
        float e1x = __expf(100.f*a.x - m1), e1y = __expf(100.f*a.y - m1);
        float e1z = __expf(100.f*a.z - m1), e1w = __expf(100.f*a.w - m1);
        float e2x = __expf(100.f*b.x - m2), e2y = __expf(100.f*b.y - m2);
        float e2z = __expf(100.f*b.z - m2), e2w = __expf(100.f*b.w - m2);
        float e3x = __expf(a.x*b.x - m3), e3y = __expf(a.y*b.y - m3);
        float e3z = __expf(a.z*b.z - m3), e3w = __expf(a.w*b.w - m3);
        s1 += (e1x + e1y) + (e1z + e1w);
        s2 += (e2x + e2y) + (e2z + e2w);
        s3 += (e3x + e3y) + (e3z + e3w);
        __half2 h0, h1;
        h0 = __floats2half2_rn(e1x, e1y); h1 = __floats2half2_rn(e1z, e1w);
        *reinterpret_cast<__half2*>(pr + i)     = h0;
        *reinterpret_cast<__half2*>(pr + i + 2) = h1;
        h0 = __floats2half2_rn(e2x, e2y); h1 = __floats2half2_rn(e2z, e2w);
        *reinterpret_cast<__half2*>(pt + i)     = h0;
        *reinterpret_cast<__half2*>(pt + i + 2) = h1;
        h0 = __floats2half2_rn(e3x, e3y); h1 = __floats2half2_rn(e3z, e3w);
        *reinterpret_cast<__half2*>(px + i)     = h0;
        *reinterpret_cast<__half2*>(px + i + 2) = h1;
    }
    #pragma unroll
    for (int o = 16; o > 0; o >>= 1) {
        s1 += __shfl_xor_sync(0xffffffffu, s1, o);
        s2 += __shfl_xor_sync(0xffffffffu, s2, o);
        s3 += __shfl_xor_sync(0xffffffffu, s3, o);
    }
    __syncthreads();
    if (lane == 0) { sm[warp][3] = s1; sm[warp][4] = s2; sm[warp][5] = s3; }
    __syncthreads();
    if (tid == 0) {
        s1 = s2 = s3 = 0.f;
        #pragma unroll
        for (int w = 0; w < 8; w++) { s1 += sm[w][3]; s2 += sm[w][4]; s3 += sm[w][5]; }
        float* o = g_stats + (size_t)row * 6;
        o[0] = m1; o[1] = s1; o[2] = m2; o[3] = s2; o[4] = m3; o[5] = s3;
    }
}

// =====================================================================
// Kernel 4: attend via mma.sync fp16 m16n8k16.
// Block tile 64(l) x 64(f); 8 warps, each 16(l) x 32(f).
// m streamed in chunks of 32 = 2 K-steps of 16.
// P: half [l][m] (pad 40). V: half transposed [f][m] (pad 40).
// grid: (F/64, L/64, HB), block 256
// =====================================================================
__global__ __launch_bounds__(256, 2)
void attend_mma_kernel(const float* __restrict__ rgbvalue,
                       const float* __restrict__ tvalue,
                       const float* __restrict__ fusevalue,
                       float* __restrict__ out)
{
    __shared__ __half Pr[64][40], Pt[64][40], Px[64][40];
    __shared__ __half Vr[64][40], Vt[64][40];   // [f][m]

    const int hb = blockIdx.z;
    const int h  = hb / Bd, b = hb % Bd;
    const int fBase = blockIdx.x * 64, lBase = blockIdx.y * 64;
    const int tid = threadIdx.x;
    const int wid = tid >> 5, lane = tid & 31;
    const int wl = wid & 3;           // l group: 16 rows
    const int wf = wid >> 2;          // f group: 32 cols
    const int r = lane >> 2, c = lane & 3;

    const __half* prh = g_PrH + ((size_t)hb * Ld + lBase) * Md;
    const __half* pth = g_PtH + ((size_t)hb * Ld + lBase) * Md;
    const __half* pxh = g_PxH + ((size_t)hb * Ld + lBase) * Md;

    float acc[4][4][4] = {};   // [out][ntile][reg]

    for (int m0 = 0; m0 < Md; m0 += 32) {
        // ---- P tiles: [l 0..63][m 0..31] halves, 8 halves per thread/stream ----
        {
            int rr  = tid >> 2;               // 0..63
            int seg = (tid & 3) * 8;          // 0,8,16,24
            size_t go = (size_t)rr * Md + m0 + seg;
            *reinterpret_cast<uint4*>(&Pr[rr][seg]) = *reinterpret_cast<const uint4*>(prh + go);
            *reinterpret_cast<uint4*>(&Pt[rr][seg]) = *reinterpret_cast<const uint4*>(pth + go);
            *reinterpret_cast<uint4*>(&Px[rr][seg]) = *reinterpret_cast<const uint4*>(pxh + go);
        }
        // ---- V tiles: read [m][f] float, store transposed [f][m] half ----
        #pragma unroll
        for (int p = 0; p < 2; p++) {
            int id = tid + p * 256;          // 0..511
            int m  = id >> 4;                // 0..31
            int f4 = (id & 15) * 4;          // 0..60
            int mm = m0 + m;
            const float* vr = (mm < Ld) ? rgbvalue + ((size_t)mm * Bd + b) * Fd
                                        : fusevalue + ((size_t)(mm - Ld) * Bd + b) * Fd;
            const float* vt = (mm < Ld) ? tvalue   + ((size_t)mm * Bd + b) * Fd
                                        : fusevalue + ((size_t)(mm - Ld) * Bd + b) * Fd;
            float4 a  = *reinterpret_cast<const float4*>(vr + fBase + f4);
            float4 bb = *reinterpret_cast<const float4*>(vt + fBase + f4);
            Vr[f4+0][m] = __float2half(a.x);  Vr[f4+1][m] = __float2half(a.y);
            Vr[f4+2][m] = __float2half(a.z);  Vr[f4+3][m] = __float2half(a.w);
            Vt[f4+0][m] = __float2half(bb.x); Vt[f4+1][m] = __float2half(bb.y);
            Vt[f4+2][m] = __float2half(bb.z); Vt[f4+3][m] = __float2half(bb.w);
        }
        __syncthreads();

        #pragma unroll
        for (int ks = 0; ks < 2; ks++) {
            const int k0 = ks * 16;
            const int la = wl * 16 + r;
            const int kc = k0 + 2 * c;
            // A fragments (m16k16 fp16): half2 at (row, kc), (row+8, kc), (row, kc+8), (row+8, kc+8)
            uint32_t ar0 = *reinterpret_cast<const uint32_t*>(&Pr[la  ][kc]);
            uint32_t ar1 = *reinterpret_cast<const uint32_t*>(&Pr[la+8][kc]);
            uint32_t ar2 = *reinterpret_cast<const uint32_t*>(&Pr[la  ][kc+8]);
            uint32_t ar3 = *reinterpret_cast<const uint32_t*>(&Pr[la+8][kc+8]);
            uint32_t at0 = *reinterpret_cast<const uint32_t*>(&Pt[la  ][kc]);
            uint32_t at1 = *reinterpret_cast<const uint32_t*>(&Pt[la+8][kc]);
            uint32_t at2 = *reinterpret_cast<const uint32_t*>(&Pt[la  ][kc+8]);
            uint32_t at3 = *reinterpret_cast<const uint32_t*>(&Pt[la+8][kc+8]);
            uint32_t ax0 = *reinterpret_cast<const uint32_t*>(&Px[la  ][kc]);
            uint32_t ax1 = *reinterpret_cast<const uint32_t*>(&Px[la+8][kc]);
            uint32_t ax2 = *reinterpret_cast<const uint32_t*>(&Px[la  ][kc+8]);
            uint32_t ax3 = *reinterpret_cast<const uint32_t*>(&Px[la+8][kc+8]);
            #pragma unroll
            for (int nt = 0; nt < 4; nt++) {
                const int fc = wf * 32 + nt * 8 + r;
                // B fragments (k16n8 col-major): half2 (k=kc, n=fc), (k=kc+8, n=fc)
                uint32_t br0 = *reinterpret_cast<const uint32_t*>(&Vr[fc][kc]);
                uint32_t br1 = *reinterpret_cast<const uint32_t*>(&Vr[fc][kc+8]);
                uint32_t bt0 = *reinterpret_cast<const uint32_t*>(&Vt[fc][kc]);
                uint32_t bt1 = *reinterpret_cast<const uint32_t*>(&Vt[fc][kc+8]);
                mma_f16(acc[0][nt], ar0, ar1, ar2, ar3, br0, br1);   // self_rgb
                mma_f16(acc[1][nt], at0, at1, at2, at3, bt0, bt1);   // self_t
                mma_f16(acc[2][nt], ax0, ax1, ax2, ax3, bt0, bt1);   // cross_rgb
                mma_f16(acc[3][nt], ax0, ax1, ax2, ax3, br0, br1);   // cross_t
            }
        }
        __syncthreads();
    }

    // ---- Epilogue: scale by 1/sum, write float2 per (out, ntile, row-half) ----
    const size_t OSZ = (size_t)Ld * Bd * HFd;
    const int l0 = lBase + wl * 16 + r;
    const int l1 = l0 + 8;
    const float* st0 = g_stats + ((size_t)hb * Ld + l0) * 6;
    const float* st1 = g_stats + ((size_t)hb * Ld + l1) * 6;
    const float inv0[4] = {1.f/st0[1], 1.f/st0[3], 1.f/st0[5], 1.f/st0[5]};
    const float inv1[4] = {1.f/st1[1], 1.f/st1[3], 1.f/st1[5], 1.f/st1[5]};
    const size_t base0 = ((size_t)l0 * Bd + b) * HFd + (size_t)h * Fd;
    const size_t base1 = ((size_t)l1 * Bd + b) * HFd + (size_t)h * Fd;
    #pragma unroll
    for (int d = 0; d < 4; d++) {
        #pragma unroll
        for (int nt = 0; nt < 4; nt++) {
            int f = fBase + wf * 32 + nt * 8 + 2 * c;
            *reinterpret_cast<float2*>(out + d*OSZ + base0 + f) =
                make_float2(acc[d][nt][0] * inv0[d], acc[d][nt][1] * inv0[d]);
            *reinterpret_cast<float2*>(out + d*OSZ + base1 + f) =
                make_float2(acc[d][nt][2] * inv1[d], acc[d][nt][3] * inv1[d]);
        }
    }
}

// =====================================================================
extern "C" void kernel_launch(void* const* d_in, const int* in_sizes, int n_in,
                              void* d_out, int out_size)
{
    const float* rgbquery  = (const float*)d_in[0];
    const float* rgbkey    = (const float*)d_in[1];
    const float* rgbvalue  = (const float*)d_in[2];
    const float* tquery    = (const float*)d_in[3];
    const float* tkey      = (const float*)d_in[4];
    const float* tvalue    = (const float*)d_in[5];
    const float* fusekey   = (const float*)d_in[6];
    const float* fusevalue = (const float*)d_in[7];
    const float* WK_w      = (const float*)d_in[8];
    const float* WK_b      = (const float*)d_in[9];
    float* out = (float*)d_out;

    proj_kernel<<<dim3(384, Hd), 256>>>(rgbquery, tquery, rgbkey, tkey, fusekey, WK_w, WK_b);

    dot_kernel<<<dim3(Md/64, Ld/64, 2*HBd), 256>>>();

    stats_kernel<<<HBd*Ld, 256>>>();

    attend_mma_kernel<<<dim3(Fd/64, Ld/64, HBd), 256>>>(rgbvalue, tvalue, fusevalue, out);
}

// round 6
// speedup vs baseline: 2.9845x; 1.4244x over previous
#include <cuda_runtime.h>
#include <cuda_fp16.h>
#include <cstdint>
#include <math.h>

// Problem constants
#define Ld  1024
#define Bd  4
#define Fd  512
#define Hd  8
#define Kd  64
#define Md  2048          // Lk + Lfuse
#define HBd (Hd*Bd)       // 32
#define HFd (Hd*Fd)       // 4096

typedef unsigned long long ull;

// ---------------- scratch (device globals; no allocs allowed) ----------------
__device__ float  g_RQ [HBd*Ld*Kd];
__device__ float  g_TQ [HBd*Ld*Kd];
__device__ float  g_FK [HBd*Md*Kd];
__device__ float  g_FK1[HBd*Md*Kd];
__device__ float  g_Srgb[(size_t)HBd*Ld*Md];     // raw dots (fp32)
__device__ float  g_St  [(size_t)HBd*Ld*Md];     // raw dots (fp32)
__device__ __half g_PrH[(size_t)HBd*Ld*Md];      // exp(100*sr - m1) half
__device__ __half g_PtH[(size_t)HBd*Ld*Md];
__device__ __half g_PxH[(size_t)HBd*Ld*Md];
__device__ __half g_VrT[(size_t)Bd*Fd*Md];       // V^T half: [b][f][m], concat resolved
__device__ __half g_VtT[(size_t)Bd*Fd*Md];
__device__ float  g_pmax[(size_t)HBd*Ld*96];     // per-row partial maxes [3][32 mblks]
__device__ float  g_stats[HBd*Ld*6];

// ---------------- packed f32x2 helpers -----------------
__device__ __forceinline__ ull dupf(float x) {
    ull d; asm("mov.b64 %0, {%1, %1};" : "=l"(d) : "f"(x)); return d;
}
__device__ __forceinline__ void fma2(ull& d, ull a, ull b) {
    asm("fma.rn.f32x2 %0, %1, %2, %0;" : "+l"(d) : "l"(a), "l"(b));
}
__device__ __forceinline__ void unpack2(ull v, float& lo, float& hi) {
    asm("mov.b64 {%0, %1}, %2;" : "=f"(lo), "=f"(hi) : "l"(v));
}

// ---------------- fp16 mma.sync helper ------
__device__ __forceinline__ void mma_f16(float* c,
                                        uint32_t a0, uint32_t a1, uint32_t a2, uint32_t a3,
                                        uint32_t b0, uint32_t b1) {
    asm volatile(
        "mma.sync.aligned.m16n8k16.row.col.f32.f16.f16.f32 "
        "{%0,%1,%2,%3}, {%4,%5,%6,%7}, {%8,%9}, {%0,%1,%2,%3};"
        : "+f"(c[0]), "+f"(c[1]), "+f"(c[2]), "+f"(c[3])
        : "r"(a0), "r"(a1), "r"(a2), "r"(a3), "r"(b0), "r"(b1));
}

// ---------------- exp2 f16x2 + cp.async helpers ----------------
__device__ __forceinline__ uint32_t h2exp2u(uint32_t x) {
    uint32_t r; asm("ex2.approx.f16x2 %0, %1;" : "=r"(r) : "r"(x)); return r;
}
__device__ __forceinline__ uint32_t pack_h2(float a, float b) {
    __half2 h = __floats2half2_rn(a, b);
    return *reinterpret_cast<uint32_t*>(&h);
}
__device__ __forceinline__ float2 h2f2(uint32_t u) {
    __half2 h = *reinterpret_cast<__half2*>(&u);
    return __half22float2(h);
}
__device__ __forceinline__ uint32_t smem_u32(const void* p) {
    uint32_t a;
    asm("{ .reg .u64 t; cvta.to.shared.u64 t, %1; cvt.u32.u64 %0, t; }" : "=r"(a) : "l"(p));
    return a;
}
#define CP_ASYNC16(dst, src) \
    asm volatile("cp.async.ca.shared.global [%0], [%1], 16;" :: "r"(dst), "l"(src) : "memory")
#define CP_COMMIT() asm volatile("cp.async.commit_group;" ::: "memory")
#define CP_WAIT1()  asm volatile("cp.async.wait_group 1;" ::: "memory")

// =====================================================================
// Kernel 0: V transpose+convert: (value,fusevalue) -> half [b][f][m]
// grid: (Md/64, Fd/64, Bd*2), block 256
// =====================================================================
__global__ __launch_bounds__(256)
void vtrans_kernel(const float* __restrict__ rgbvalue,
                   const float* __restrict__ tvalue,
                   const float* __restrict__ fusevalue)
{
    __shared__ __half T[64][66];
    const int mBase = blockIdx.x * 64, fBase = blockIdx.y * 64;
    const int b = blockIdx.z & 3, sel = blockIdx.z >> 2;
    const float* v0 = sel ? tvalue : rgbvalue;
    __half* dst = sel ? g_VtT : g_VrT;
    const int tid = threadIdx.x;

    #pragma unroll
    for (int p = 0; p < 2; p++) {
        int id = tid + p * 256;
        int m  = id >> 3;
        int f8 = (id & 7) * 8;
        int mm = mBase + m;
        const float* src = (mm < Ld) ? v0 + ((size_t)mm * Bd + b) * Fd
                                     : fusevalue + ((size_t)(mm - Ld) * Bd + b) * Fd;
        float4 x = *reinterpret_cast<const float4*>(src + fBase + f8);
        float4 y = *reinterpret_cast<const float4*>(src + fBase + f8 + 4);
        T[m][f8+0] = __float2half(x.x); T[m][f8+1] = __float2half(x.y);
        T[m][f8+2] = __float2half(x.z); T[m][f8+3] = __float2half(x.w);
        T[m][f8+4] = __float2half(y.x); T[m][f8+5] = __float2half(y.y);
        T[m][f8+6] = __float2half(y.z); T[m][f8+7] = __float2half(y.w);
    }
    __syncthreads();
    #pragma unroll
    for (int p = 0; p < 2; p++) {
        int id = tid + p * 256;
        int f  = id >> 3;
        int m8 = (id & 7) * 8;
        __half tmp[8];
        #pragma unroll
        for (int k = 0; k < 8; k++) tmp[k] = T[m8 + k][f];
        *reinterpret_cast<uint4*>(dst + ((size_t)(b * Fd + fBase + f)) * Md + mBase + m8) =
            *reinterpret_cast<uint4*>(tmp);
    }
}

// =====================================================================
// Kernel 1: all four projections + L2 norm in one launch (from R5).
// =====================================================================
__global__ __launch_bounds__(256)
void proj_kernel(const float* __restrict__ rgbquery, const float* __restrict__ tquery,
                 const float* __restrict__ rgbkey,   const float* __restrict__ tkey,
                 const float* __restrict__ fusekey,
                 const float* __restrict__ Wm, const float* __restrict__ bias)
{
    __shared__ float Xs[32][68];
    __shared__ float Ws[32][68];

    const int bx = blockIdx.x;
    const float *src0, *src1;
    float* out;
    int rowBase, Lx;
    if (bx < 64)       { src0 = rgbquery; src1 = rgbquery; out = g_RQ;  rowBase = bx * 64;        Lx = Ld; }
    else if (bx < 128) { src0 = tquery;   src1 = tquery;   out = g_TQ;  rowBase = (bx-64) * 64;   Lx = Ld; }
    else if (bx < 256) { src0 = rgbkey;   src1 = fusekey;  out = g_FK;  rowBase = (bx-128) * 64;  Lx = Md; }
    else               { src0 = tkey;     src1 = fusekey;  out = g_FK1; rowBase = (bx-256) * 64;  Lx = Md; }
    const int rows0 = Ld * Bd;

    const int h = blockIdx.y;
    const int tid = threadIdx.x;
    const int tx = tid & 15, ty = tid >> 4;

    ull A[2][4] = {};

    for (int k0 = 0; k0 < Fd; k0 += 32) {
        #pragma unroll
        for (int p = 0; p < 2; p++) {
            int id = tid + p * 256;
            int r  = id >> 3;
            int c4 = (id & 7) * 4;
            int gr = rowBase + r;
            const float* xr = (gr < rows0) ? (src0 + (size_t)gr * Fd)
                                           : (src1 + (size_t)(gr - rows0) * Fd);
            float4 v = *reinterpret_cast<const float4*>(xr + k0 + c4);
            Xs[c4+0][r] = v.x; Xs[c4+1][r] = v.y; Xs[c4+2][r] = v.z; Xs[c4+3][r] = v.w;
            float4 w = *reinterpret_cast<const float4*>(Wm + (size_t)(h*64 + r) * Fd + k0 + c4);
            Ws[c4+0][r] = w.x; Ws[c4+1][r] = w.y; Ws[c4+2][r] = w.z; Ws[c4+3][r] = w.w;
        }
        __syncthreads();
        #pragma unroll
        for (int kk = 0; kk < 32; kk++) {
            ulonglong2 x2 = *reinterpret_cast<const ulonglong2*>(&Xs[kk][ty*4]);
            float4 w = *reinterpret_cast<const float4*>(&Ws[kk][tx*4]);
            ull xp[2] = {x2.x, x2.y};
            ull wd[4] = {dupf(w.x), dupf(w.y), dupf(w.z), dupf(w.w)};
            #pragma unroll
            for (int p = 0; p < 2; p++)
                #pragma unroll
                for (int j = 0; j < 4; j++)
                    fma2(A[p][j], xp[p], wd[j]);
        }
        __syncthreads();
    }

    float acc[4][4];
    #pragma unroll
    for (int p = 0; p < 2; p++)
        #pragma unroll
        for (int j = 0; j < 4; j++)
            unpack2(A[p][j], acc[2*p][j], acc[2*p+1][j]);

    #pragma unroll
    for (int j = 0; j < 4; j++) {
        float bb = bias[h*64 + tx*4 + j];
        #pragma unroll
        for (int i = 0; i < 4; i++) acc[i][j] += bb;
    }

    #pragma unroll
    for (int i = 0; i < 4; i++) {
        float s = 0.f;
        #pragma unroll
        for (int j = 0; j < 4; j++) s += acc[i][j] * acc[i][j];
        s += __shfl_xor_sync(0xffffffffu, s, 1);
        s += __shfl_xor_sync(0xffffffffu, s, 2);
        s += __shfl_xor_sync(0xffffffffu, s, 4);
        s += __shfl_xor_sync(0xffffffffu, s, 8);
        float inv = 1.0f / fmaxf(sqrtf(s), 1e-12f);
        int gr = rowBase + ty*4 + i;
        int l  = gr / Bd, b = gr % Bd;
        *reinterpret_cast<float4*>(out + ((size_t)(h*Bd + b) * Lx + l) * Kd + tx*4) =
            make_float4(acc[i][0]*inv, acc[i][1]*inv, acc[i][2]*inv, acc[i][3]*inv);
    }
}

// =====================================================================
// Kernel 2: fused dot — both streams per tile + inline partial maxes.
// grid: (Md/64, Ld/64, HBd), block 256, dynamic smem 4*64*68*4 B
// =====================================================================
#define DOT_SMEM (4*64*68*4)
__global__ __launch_bounds__(256)
void dot_kernel()
{
    extern __shared__ float dsm[];
    float (*Qr)[68] = reinterpret_cast<float(*)[68]>(dsm);
    float (*Qt)[68] = reinterpret_cast<float(*)[68]>(dsm + 64*68);
    float (*Kr)[68] = reinterpret_cast<float(*)[68]>(dsm + 2*64*68);
    float (*Kt)[68] = reinterpret_cast<float(*)[68]>(dsm + 3*64*68);

    const int hb = blockIdx.z;
    const int mBase = blockIdx.x * 64, lBase = blockIdx.y * 64;
    const int mblk = blockIdx.x;
    const int tid = threadIdx.x;
    const int tx = tid & 15, ty = tid >> 4;

    const float* Qrp = g_RQ  + (size_t)hb * Ld * Kd + (size_t)lBase * Kd;
    const float* Qtp = g_TQ  + (size_t)hb * Ld * Kd + (size_t)lBase * Kd;
    const float* Krp = g_FK  + (size_t)hb * Md * Kd + (size_t)mBase * Kd;
    const float* Ktp = g_FK1 + (size_t)hb * Md * Kd + (size_t)mBase * Kd;

    #pragma unroll
    for (int p = 0; p < 4; p++) {
        int id = tid + p * 256;
        int r  = id >> 4;
        int c4 = (id & 15) * 4;
        float4 v;
        v = *reinterpret_cast<const float4*>(Qrp + (size_t)r * Kd + c4);
        Qr[c4+0][r] = v.x; Qr[c4+1][r] = v.y; Qr[c4+2][r] = v.z; Qr[c4+3][r] = v.w;
        v = *reinterpret_cast<const float4*>(Qtp + (size_t)r * Kd + c4);
        Qt[c4+0][r] = v.x; Qt[c4+1][r] = v.y; Qt[c4+2][r] = v.z; Qt[c4+3][r] = v.w;
        v = *reinterpret_cast<const float4*>(Krp + (size_t)r * Kd + c4);
        Kr[c4+0][r] = v.x; Kr[c4+1][r] = v.y; Kr[c4+2][r] = v.z; Kr[c4+3][r] = v.w;
        v = *reinterpret_cast<const float4*>(Ktp + (size_t)r * Kd + c4);
        Kt[c4+0][r] = v.x; Kt[c4+1][r] = v.y; Kt[c4+2][r] = v.z; Kt[c4+3][r] = v.w;
    }
    __syncthreads();

    ull Ar[2][4] = {}, At[2][4] = {};
    #pragma unroll 8
    for (int kk = 0; kk < 64; kk++) {
        ulonglong2 qr2 = *reinterpret_cast<const ulonglong2*>(&Qr[kk][ty*4]);
        ulonglong2 qt2 = *reinterpret_cast<const ulonglong2*>(&Qt[kk][ty*4]);
        float4 kr = *reinterpret_cast<const float4*>(&Kr[kk][tx*4]);
        float4 kt = *reinterpret_cast<const float4*>(&Kt[kk][tx*4]);
        ull qrp[2] = {qr2.x, qr2.y}, qtp[2] = {qt2.x, qt2.y};
        ull krd[4] = {dupf(kr.x), dupf(kr.y), dupf(kr.z), dupf(kr.w)};
        ull ktd[4] = {dupf(kt.x), dupf(kt.y), dupf(kt.z), dupf(kt.w)};
        #pragma unroll
        for (int p = 0; p < 2; p++)
            #pragma unroll
            for (int j = 0; j < 4; j++) {
                fma2(Ar[p][j], qrp[p], krd[j]);
                fma2(At[p][j], qtp[p], ktd[j]);
            }
    }

    float ar[4][4], at[4][4];
    #pragma unroll
    for (int p = 0; p < 2; p++)
        #pragma unroll
        for (int j = 0; j < 4; j++) {
            unpack2(Ar[p][j], ar[2*p][j], ar[2*p+1][j]);
            unpack2(At[p][j], at[2*p][j], at[2*p+1][j]);
        }

    #pragma unroll
    for (int i = 0; i < 4; i++) {
        int l = lBase + ty*4 + i;
        *reinterpret_cast<float4*>(g_Srgb + ((size_t)hb * Ld + l) * Md + mBase + tx*4) =
            make_float4(ar[i][0], ar[i][1], ar[i][2], ar[i][3]);
        *reinterpret_cast<float4*>(g_St + ((size_t)hb * Ld + l) * Md + mBase + tx*4) =
            make_float4(at[i][0], at[i][1], at[i][2], at[i][3]);
    }

    // partial maxes over this tile's 64 m-columns, per row
    #pragma unroll
    for (int i = 0; i < 4; i++) {
        float p1 = ar[i][0], p2 = at[i][0], p3 = ar[i][0]*at[i][0];
        #pragma unroll
        for (int j = 1; j < 4; j++) {
            p1 = fmaxf(p1, ar[i][j]);
            p2 = fmaxf(p2, at[i][j]);
            p3 = fmaxf(p3, ar[i][j]*at[i][j]);
        }
        #pragma unroll
        for (int o = 8; o > 0; o >>= 1) {
            p1 = fmaxf(p1, __shfl_xor_sync(0xffffffffu, p1, o));
            p2 = fmaxf(p2, __shfl_xor_sync(0xffffffffu, p2, o));
            p3 = fmaxf(p3, __shfl_xor_sync(0xffffffffu, p3, o));
        }
        if (tx == 0) {
            size_t row = (size_t)hb * Ld + lBase + ty*4 + i;
            g_pmax[row*96 +      mblk] = p1;
            g_pmax[row*96 + 32 + mblk] = p2;
            g_pmax[row*96 + 64 + mblk] = p3;
        }
    }
}

// =====================================================================
// Kernel 3: stats — read partial maxes, single pass exp via ex2.f16x2,
// fp32 sums, store half P. grid: HB*L blocks of 256
// =====================================================================
__global__ __launch_bounds__(256)
void stats_kernel()
{
    const int row = blockIdx.x;
    const float* sr = g_Srgb + (size_t)row * Md;
    const float* st = g_St   + (size_t)row * Md;
    __half* pr = g_PrH + (size_t)row * Md;
    __half* pt = g_PtH + (size_t)row * Md;
    __half* px = g_PxH + (size_t)row * Md;
    const int tid = threadIdx.x;
    const int lane = tid & 31, wid = tid >> 5;
    __shared__ float smax[3];
    __shared__ float sm[8][3];

    if (wid < 3) {
        float v = g_pmax[(size_t)row * 96 + wid*32 + lane];
        #pragma unroll
        for (int o = 16; o > 0; o >>= 1)
            v = fmaxf(v, __shfl_xor_sync(0xffffffffu, v, o));
        if (lane == 0) smax[wid] = v;
    }
    __syncthreads();

    const float L2E = 1.44269504088896340736f;
    const float m1 = 100.f * smax[0], m2 = 100.f * smax[1], m3 = smax[2];
    const float c100 = 100.f * L2E;
    const float mm1 = m1 * L2E, mm2 = m2 * L2E, mm3 = m3 * L2E;

    float s1 = 0.f, s2 = 0.f, s3 = 0.f;
    #pragma unroll
    for (int it = 0; it < 2; it++) {
        int i = (tid + it * 256) * 4;
        float4 a = *reinterpret_cast<const float4*>(sr + i);
        float4 b = *reinterpret_cast<const float4*>(st + i);

        uint32_t u0 = h2exp2u(pack_h2(fmaf(c100, a.x, -mm1), fmaf(c100, a.y, -mm1)));
        uint32_t u1 = h2exp2u(pack_h2(fmaf(c100, a.z, -mm1), fmaf(c100, a.w, -mm1)));
        *reinterpret_cast<uint2*>(pr + i) = make_uint2(u0, u1);
        float2 f0 = h2f2(u0), f1 = h2f2(u1);
        s1 += (f0.x + f0.y) + (f1.x + f1.y);

        u0 = h2exp2u(pack_h2(fmaf(c100, b.x, -mm2), fmaf(c100, b.y, -mm2)));
        u1 = h2exp2u(pack_h2(fmaf(c100, b.z, -mm2), fmaf(c100, b.w, -mm2)));
        *reinterpret_cast<uint2*>(pt + i) = make_uint2(u0, u1);
        f0 = h2f2(u0); f1 = h2f2(u1);
        s2 += (f0.x + f0.y) + (f1.x + f1.y);

        u0 = h2exp2u(pack_h2(fmaf(L2E, a.x*b.x, -mm3), fmaf(L2E, a.y*b.y, -mm3)));
        u1 = h2exp2u(pack_h2(fmaf(L2E, a.z*b.z, -mm3), fmaf(L2E, a.w*b.w, -mm3)));
        *reinterpret_cast<uint2*>(px + i) = make_uint2(u0, u1);
        f0 = h2f2(u0); f1 = h2f2(u1);
        s3 += (f0.x + f0.y) + (f1.x + f1.y);
    }
    #pragma unroll
    for (int o = 16; o > 0; o >>= 1) {
        s1 += __shfl_xor_sync(0xffffffffu, s1, o);
        s2 += __shfl_xor_sync(0xffffffffu, s2, o);
        s3 += __shfl_xor_sync(0xffffffffu, s3, o);
    }
    if (lane == 0) { sm[wid][0] = s1; sm[wid][1] = s2; sm[wid][2] = s3; }
    __syncthreads();
    if (tid == 0) {
        s1 = s2 = s3 = 0.f;
        #pragma unroll
        for (int w = 0; w < 8; w++) { s1 += sm[w][0]; s2 += sm[w][1]; s3 += sm[w][2]; }
        float* o = g_stats + (size_t)row * 6;
        o[0] = m1; o[1] = s1; o[2] = m2; o[3] = s2; o[4] = m3; o[5] = s3;
    }
}

// =====================================================================
// Kernel 4: attend, fp16 mma + cp.async double buffering. Tiles all half.
// grid: (F/64, L/64, HB), block 256, dynamic smem 51200 B
// =====================================================================
#define AST    40                    // half stride per tile row
#define ATILE  (64*AST)              // halves per tile
#define ASTAGE (5*ATILE)             // halves per stage
#define ATT_SMEM (2*ASTAGE*2)        // bytes

__global__ __launch_bounds__(256, 2)
void attend_mma_kernel(float* __restrict__ out)
{
    extern __shared__ __half ash[];
    const int hb = blockIdx.z;
    const int h  = hb / Bd, b = hb % Bd;
    const int fBase = blockIdx.x * 64, lBase = blockIdx.y * 64;
    const int tid = threadIdx.x;
    const int wid = tid >> 5, lane = tid & 31;
    const int wl = wid & 3, wf = wid >> 2;
    const int r = lane >> 2, c = lane & 3;

    const __half* s0 = g_PrH + ((size_t)hb * Ld + lBase) * Md;
    const __half* s1 = g_PtH + ((size_t)hb * Ld + lBase) * Md;
    const __half* s2 = g_PxH + ((size_t)hb * Ld + lBase) * Md;
    const __half* s3 = g_VrT + ((size_t)(b * Fd + fBase)) * Md;
    const __half* s4 = g_VtT + ((size_t)(b * Fd + fBase)) * Md;

    const uint32_t sbase = smem_u32(ash);
    const int frow = tid >> 2, fseg = tid & 3;           // each thread: 1 row slot, 16B seg
    const uint32_t dlocal = (uint32_t)(frow * AST + fseg * 8) * 2;

    float acc[4][4][4] = {};

    // prologue: fill stage 0 with chunk 0
    {
        size_t go = (size_t)frow * Md + fseg * 8;
        uint32_t dst = sbase + dlocal;
        CP_ASYNC16(dst + 0*ATILE*2, s0 + go);
        CP_ASYNC16(dst + 1*ATILE*2, s1 + go);
        CP_ASYNC16(dst + 2*ATILE*2, s2 + go);
        CP_ASYNC16(dst + 3*ATILE*2, s3 + go);
        CP_ASYNC16(dst + 4*ATILE*2, s4 + go);
    }
    CP_COMMIT();

    for (int cc = 0; cc < Md/32; cc++) {
        if (cc + 1 < Md/32) {
            size_t go = (size_t)frow * Md + (cc + 1) * 32 + fseg * 8;
            uint32_t dst = sbase + (uint32_t)(((cc + 1) & 1) * ASTAGE) * 2 + dlocal;
            CP_ASYNC16(dst + 0*ATILE*2, s0 + go);
            CP_ASYNC16(dst + 1*ATILE*2, s1 + go);
            CP_ASYNC16(dst + 2*ATILE*2, s2 + go);
            CP_ASYNC16(dst + 3*ATILE*2, s3 + go);
            CP_ASYNC16(dst + 4*ATILE*2, s4 + go);
        }
        CP_COMMIT();
        CP_WAIT1();
        __syncthreads();

        const __half* sb = ash + (cc & 1) * ASTAGE;
        typedef const __half (*T40)[AST];
        T40 PrS = (T40)sb;
        T40 PtS = (T40)(sb + ATILE);
        T40 PxS = (T40)(sb + 2*ATILE);
        T40 VrS = (T40)(sb + 3*ATILE);     // [f][m]
        T40 VtS = (T40)(sb + 4*ATILE);

        #pragma unroll
        for (int ks = 0; ks < 2; ks++) {
            const int kc = ks * 16 + 2 * c;
            const int la = wl * 16 + r;
            uint32_t ar0 = *reinterpret_cast<const uint32_t*>(&PrS[la  ][kc]);
            uint32_t ar1 = *reinterpret_cast<const uint32_t*>(&PrS[la+8][kc]);
            uint32_t ar2 = *reinterpret_cast<const uint32_t*>(&PrS[la  ][kc+8]);
            uint32_t ar3 = *reinterpret_cast<const uint32_t*>(&PrS[la+8][kc+8]);
            uint32_t at0 = *reinterpret_cast<const uint32_t*>(&PtS[la  ][kc]);
            uint32_t at1 = *reinterpret_cast<const uint32_t*>(&PtS[la+8][kc]);
            uint32_t at2 = *reinterpret_cast<const uint32_t*>(&PtS[la  ][kc+8]);
            uint32_t at3 = *reinterpret_cast<const uint32_t*>(&PtS[la+8][kc+8]);
            uint32_t ax0 = *reinterpret_cast<const uint32_t*>(&PxS[la  ][kc]);
            uint32_t ax1 = *reinterpret_cast<const uint32_t*>(&PxS[la+8][kc]);
            uint32_t ax2 = *reinterpret_cast<const uint32_t*>(&PxS[la  ][kc+8]);
            uint32_t ax3 = *reinterpret_cast<const uint32_t*>(&PxS[la+8][kc+8]);
            #pragma unroll
            for (int nt = 0; nt < 4; nt++) {
                const int fc = wf * 32 + nt * 8 + r;
                uint32_t br0 = *reinterpret_cast<const uint32_t*>(&VrS[fc][kc]);
                uint32_t br1 = *reinterpret_cast<const uint32_t*>(&VrS[fc][kc+8]);
                uint32_t bt0 = *reinterpret_cast<const uint32_t*>(&VtS[fc][kc]);
                uint32_t bt1 = *reinterpret_cast<const uint32_t*>(&VtS[fc][kc+8]);
                mma_f16(acc[0][nt], ar0, ar1, ar2, ar3, br0, br1);
                mma_f16(acc[1][nt], at0, at1, at2, at3, bt0, bt1);
                mma_f16(acc[2][nt], ax0, ax1, ax2, ax3, bt0, bt1);
                mma_f16(acc[3][nt], ax0, ax1, ax2, ax3, br0, br1);
            }
        }
        __syncthreads();
    }

    const size_t OSZ = (size_t)Ld * Bd * HFd;
    const int l0 = lBase + wl * 16 + r;
    const int l1 = l0 + 8;
    const float* st0 = g_stats + ((size_t)hb * Ld + l0) * 6;
    const float* st1 = g_stats + ((size_t)hb * Ld + l1) * 6;
    const float inv0[4] = {1.f/st0[1], 1.f/st0[3], 1.f/st0[5], 1.f/st0[5]};
    const float inv1[4] = {1.f/st1[1], 1.f/st1[3], 1.f/st1[5], 1.f/st1[5]};
    const size_t base0 = ((size_t)l0 * Bd + b) * HFd + (size_t)h * Fd;
    const size_t base1 = ((size_t)l1 * Bd + b) * HFd + (size_t)h * Fd;
    #pragma unroll
    for (int d = 0; d < 4; d++) {
        #pragma unroll
        for (int nt = 0; nt < 4; nt++) {
            int f = fBase + wf * 32 + nt * 8 + 2 * c;
            *reinterpret_cast<float2*>(out + d*OSZ + base0 + f) =
                make_float2(acc[d][nt][0] * inv0[d], acc[d][nt][1] * inv0[d]);
            *reinterpret_cast<float2*>(out + d*OSZ + base1 + f) =
                make_float2(acc[d][nt][2] * inv1[d], acc[d][nt][3] * inv1[d]);
        }
    }
}

// =====================================================================
extern "C" void kernel_launch(void* const* d_in, const int* in_sizes, int n_in,
                              void* d_out, int out_size)
{
    const float* rgbquery  = (const float*)d_in[0];
    const float* rgbkey    = (const float*)d_in[1];
    const float* rgbvalue  = (const float*)d_in[2];
    const float* tquery    = (const float*)d_in[3];
    const float* tkey      = (const float*)d_in[4];
    const float* tvalue    = (const float*)d_in[5];
    const float* fusekey   = (const float*)d_in[6];
    const float* fusevalue = (const float*)d_in[7];
    const float* WK_w      = (const float*)d_in[8];
    const float* WK_b      = (const float*)d_in[9];
    float* out = (float*)d_out;

    cudaFuncSetAttribute(dot_kernel, cudaFuncAttributeMaxDynamicSharedMemorySize, DOT_SMEM);
    cudaFuncSetAttribute(attend_mma_kernel, cudaFuncAttributeMaxDynamicSharedMemorySize, ATT_SMEM);

    vtrans_kernel<<<dim3(Md/64, Fd/64, Bd*2), 256>>>(rgbvalue, tvalue, fusevalue);
    proj_kernel<<<dim3(384, Hd), 256>>>(rgbquery, tquery, rgbkey, tkey, fusekey, WK_w, WK_b);
    dot_kernel<<<dim3(Md/64, Ld/64, HBd), 256, DOT_SMEM>>>();
    stats_kernel<<<HBd*Ld, 256>>>();
    attend_mma_kernel<<<dim3(Fd/64, Ld/64, HBd), 256, ATT_SMEM>>>(out);
}

// round 7
// speedup vs baseline: 3.9600x; 1.3269x over previous
#include <cuda_runtime.h>
#include <cuda_fp16.h>
#include <cstdint>
#include <math.h>

// Problem constants
#define Ld  1024
#define Bd  4
#define Fd  512
#define Hd  8
#define Kd  64
#define Md  2048          // Lk + Lfuse
#define HBd (Hd*Bd)       // 32
#define HFd (Hd*Fd)       // 4096

typedef unsigned long long ull;

// ---------------- scratch (device globals; no allocs allowed) ----------------
__device__ __half g_QrHi[HBd*Ld*Kd], g_QrLo[HBd*Ld*Kd];   // Q/K in split fp16
__device__ __half g_QtHi[HBd*Ld*Kd], g_QtLo[HBd*Ld*Kd];
__device__ __half g_KrHi[HBd*Md*Kd], g_KrLo[HBd*Md*Kd];
__device__ __half g_KtHi[HBd*Md*Kd], g_KtLo[HBd*Md*Kd];
__device__ float  g_Srgb[(size_t)HBd*Ld*Md];     // raw dots (fp32)
__device__ float  g_St  [(size_t)HBd*Ld*Md];
__device__ __half g_PrH[(size_t)HBd*Ld*Md];      // unnormalized softmax numerators (half)
__device__ __half g_PtH[(size_t)HBd*Ld*Md];
__device__ __half g_PxH[(size_t)HBd*Ld*Md];
__device__ __half g_VrT[(size_t)Bd*Fd*Md];       // V^T half: [b][f][m]
__device__ __half g_VtT[(size_t)Bd*Fd*Md];
__device__ float  g_pmax[(size_t)HBd*Ld*96];     // per-row partial maxes [3][32 mblks]
__device__ float  g_stats[HBd*Ld*6];

// ---------------- packed f32x2 helpers -----------------
__device__ __forceinline__ ull dupf(float x) {
    ull d; asm("mov.b64 %0, {%1, %1};" : "=l"(d) : "f"(x)); return d;
}
__device__ __forceinline__ void fma2(ull& d, ull a, ull b) {
    asm("fma.rn.f32x2 %0, %1, %2, %0;" : "+l"(d) : "l"(a), "l"(b));
}
__device__ __forceinline__ void unpack2(ull v, float& lo, float& hi) {
    asm("mov.b64 {%0, %1}, %2;" : "=f"(lo), "=f"(hi) : "l"(v));
}

// ---------------- mma / ldmatrix / exp2 / cp.async helpers ----------------
__device__ __forceinline__ void mma_f16(float* c,
                                        uint32_t a0, uint32_t a1, uint32_t a2, uint32_t a3,
                                        uint32_t b0, uint32_t b1) {
    asm volatile(
        "mma.sync.aligned.m16n8k16.row.col.f32.f16.f16.f32 "
        "{%0,%1,%2,%3}, {%4,%5,%6,%7}, {%8,%9}, {%0,%1,%2,%3};"
        : "+f"(c[0]), "+f"(c[1]), "+f"(c[2]), "+f"(c[3])
        : "r"(a0), "r"(a1), "r"(a2), "r"(a3), "r"(b0), "r"(b1));
}
__device__ __forceinline__ void ldsm_x4(uint32_t* r, uint32_t addr) {
    asm volatile("ldmatrix.sync.aligned.m8n8.x4.shared.b16 {%0,%1,%2,%3}, [%4];"
                 : "=r"(r[0]), "=r"(r[1]), "=r"(r[2]), "=r"(r[3]) : "r"(addr));
}
__device__ __forceinline__ uint32_t h2exp2u(uint32_t x) {
    uint32_t r; asm("ex2.approx.f16x2 %0, %1;" : "=r"(r) : "r"(x)); return r;
}
__device__ __forceinline__ uint32_t pack_h2(float a, float b) {
    __half2 h = __floats2half2_rn(a, b);
    return *reinterpret_cast<uint32_t*>(&h);
}
__device__ __forceinline__ float2 h2f2(uint32_t u) {
    __half2 h = *reinterpret_cast<__half2*>(&u);
    return __half22float2(h);
}
__device__ __forceinline__ uint32_t smem_u32(const void* p) {
    uint32_t a;
    asm("{ .reg .u64 t; cvta.to.shared.u64 t, %1; cvt.u32.u64 %0, t; }" : "=r"(a) : "l"(p));
    return a;
}
#define CP_ASYNC16(dst, src) \
    asm volatile("cp.async.ca.shared.global [%0], [%1], 16;" :: "r"(dst), "l"(src) : "memory")
#define CP_COMMIT() asm volatile("cp.async.commit_group;" ::: "memory")
#define CP_WAIT1()  asm volatile("cp.async.wait_group 1;" ::: "memory")
#define CP_WAIT0()  asm volatile("cp.async.wait_group 0;" ::: "memory")

// =====================================================================
// Kernel 0: V transpose+convert -> half [b][f][m]
// =====================================================================
__global__ __launch_bounds__(256)
void vtrans_kernel(const float* __restrict__ rgbvalue,
                   const float* __restrict__ tvalue,
                   const float* __restrict__ fusevalue)
{
    __shared__ __half T[64][66];
    const int mBase = blockIdx.x * 64, fBase = blockIdx.y * 64;
    const int b = blockIdx.z & 3, sel = blockIdx.z >> 2;
    const float* v0 = sel ? tvalue : rgbvalue;
    __half* dst = sel ? g_VtT : g_VrT;
    const int tid = threadIdx.x;

    #pragma unroll
    for (int p = 0; p < 2; p++) {
        int id = tid + p * 256;
        int m  = id >> 3;
        int f8 = (id & 7) * 8;
        int mm = mBase + m;
        const float* src = (mm < Ld) ? v0 + ((size_t)mm * Bd + b) * Fd
                                     : fusevalue + ((size_t)(mm - Ld) * Bd + b) * Fd;
        float4 x = *reinterpret_cast<const float4*>(src + fBase + f8);
        float4 y = *reinterpret_cast<const float4*>(src + fBase + f8 + 4);
        T[m][f8+0] = __float2half(x.x); T[m][f8+1] = __float2half(x.y);
        T[m][f8+2] = __float2half(x.z); T[m][f8+3] = __float2half(x.w);
        T[m][f8+4] = __float2half(y.x); T[m][f8+5] = __float2half(y.y);
        T[m][f8+6] = __float2half(y.z); T[m][f8+7] = __float2half(y.w);
    }
    __syncthreads();
    #pragma unroll
    for (int p = 0; p < 2; p++) {
        int id = tid + p * 256;
        int f  = id >> 3;
        int m8 = (id & 7) * 8;
        __half tmp[8];
        #pragma unroll
        for (int k = 0; k < 8; k++) tmp[k] = T[m8 + k][f];
        *reinterpret_cast<uint4*>(dst + ((size_t)(b * Fd + fBase + f)) * Md + mBase + m8) =
            *reinterpret_cast<uint4*>(tmp);
    }
}

// =====================================================================
// Kernel 1: projections + L2 norm; epilogue writes half hi/lo split.
// grid: (384, 8)
// =====================================================================
__global__ __launch_bounds__(256)
void proj_kernel(const float* __restrict__ rgbquery, const float* __restrict__ tquery,
                 const float* __restrict__ rgbkey,   const float* __restrict__ tkey,
                 const float* __restrict__ fusekey,
                 const float* __restrict__ Wm, const float* __restrict__ bias)
{
    __shared__ float Xs[32][68];
    __shared__ float Ws[32][68];

    const int bx = blockIdx.x;
    const float *src0, *src1;
    __half *oHi, *oLo;
    int rowBase, Lx;
    if (bx < 64)       { src0 = rgbquery; src1 = rgbquery; oHi = g_QrHi; oLo = g_QrLo; rowBase = bx * 64;       Lx = Ld; }
    else if (bx < 128) { src0 = tquery;   src1 = tquery;   oHi = g_QtHi; oLo = g_QtLo; rowBase = (bx-64) * 64;  Lx = Ld; }
    else if (bx < 256) { src0 = rgbkey;   src1 = fusekey;  oHi = g_KrHi; oLo = g_KrLo; rowBase = (bx-128) * 64; Lx = Md; }
    else               { src0 = tkey;     src1 = fusekey;  oHi = g_KtHi; oLo = g_KtLo; rowBase = (bx-256) * 64; Lx = Md; }
    const int rows0 = Ld * Bd;

    const int h = blockIdx.y;
    const int tid = threadIdx.x;
    const int tx = tid & 15, ty = tid >> 4;

    ull A[2][4] = {};

    for (int k0 = 0; k0 < Fd; k0 += 32) {
        #pragma unroll
        for (int p = 0; p < 2; p++) {
            int id = tid + p * 256;
            int r  = id >> 3;
            int c4 = (id & 7) * 4;
            int gr = rowBase + r;
            const float* xr = (gr < rows0) ? (src0 + (size_t)gr * Fd)
                                           : (src1 + (size_t)(gr - rows0) * Fd);
            float4 v = *reinterpret_cast<const float4*>(xr + k0 + c4);
            Xs[c4+0][r] = v.x; Xs[c4+1][r] = v.y; Xs[c4+2][r] = v.z; Xs[c4+3][r] = v.w;
            float4 w = *reinterpret_cast<const float4*>(Wm + (size_t)(h*64 + r) * Fd + k0 + c4);
            Ws[c4+0][r] = w.x; Ws[c4+1][r] = w.y; Ws[c4+2][r] = w.z; Ws[c4+3][r] = w.w;
        }
        __syncthreads();
        #pragma unroll
        for (int kk = 0; kk < 32; kk++) {
            ulonglong2 x2 = *reinterpret_cast<const ulonglong2*>(&Xs[kk][ty*4]);
            float4 w = *reinterpret_cast<const float4*>(&Ws[kk][tx*4]);
            ull xp[2] = {x2.x, x2.y};
            ull wd[4] = {dupf(w.x), dupf(w.y), dupf(w.z), dupf(w.w)};
            #pragma unroll
            for (int p = 0; p < 2; p++)
                #pragma unroll
                for (int j = 0; j < 4; j++)
                    fma2(A[p][j], xp[p], wd[j]);
        }
        __syncthreads();
    }

    float acc[4][4];
    #pragma unroll
    for (int p = 0; p < 2; p++)
        #pragma unroll
        for (int j = 0; j < 4; j++)
            unpack2(A[p][j], acc[2*p][j], acc[2*p+1][j]);

    #pragma unroll
    for (int j = 0; j < 4; j++) {
        float bb = bias[h*64 + tx*4 + j];
        #pragma unroll
        for (int i = 0; i < 4; i++) acc[i][j] += bb;
    }

    #pragma unroll
    for (int i = 0; i < 4; i++) {
        float s = 0.f;
        #pragma unroll
        for (int j = 0; j < 4; j++) s += acc[i][j] * acc[i][j];
        s += __shfl_xor_sync(0xffffffffu, s, 1);
        s += __shfl_xor_sync(0xffffffffu, s, 2);
        s += __shfl_xor_sync(0xffffffffu, s, 4);
        s += __shfl_xor_sync(0xffffffffu, s, 8);
        float inv = 1.0f / fmaxf(sqrtf(s), 1e-12f);
        int gr = rowBase + ty*4 + i;
        int l  = gr / Bd, b = gr % Bd;
        size_t off = ((size_t)(h*Bd + b) * Lx + l) * Kd + tx*4;
        float v[4], hf[4];
        __half hh[4], hl[4];
        #pragma unroll
        for (int j = 0; j < 4; j++) {
            v[j] = acc[i][j] * inv;
            hh[j] = __float2half_rn(v[j]);
            hf[j] = __half2float(hh[j]);
            hl[j] = __float2half_rn(v[j] - hf[j]);
        }
        *reinterpret_cast<uint2*>(oHi + off) =
            make_uint2(pack_h2(__half2float(hh[0]), __half2float(hh[1])),
                       pack_h2(__half2float(hh[2]), __half2float(hh[3])));
        *reinterpret_cast<uint2*>(oLo + off) =
            make_uint2(pack_h2(__half2float(hl[0]), __half2float(hl[1])),
                       pack_h2(__half2float(hl[2]), __half2float(hl[3])));
    }
}

// =====================================================================
// Kernel 2: dot via split-fp16 mma: s = qh*kh + qh*kl + ql*kh (fp32 acc).
// Block: 128l x 64m, K=64 one-shot. 8 warps, each 16l x 64m.
// Writes fp32 S + per-row partial maxes for 3 softmax streams.
// grid: (Md/64, Ld/128, HBd), block 256, dynamic smem 110592 B
// =====================================================================
#define DST 72                         // half stride in dot tiles
#define DQT (128*DST)                  // halves per Q tile
#define DKT (64*DST)
#define DOT_SMEM ((4*DQT + 4*DKT)*2)   // 110592 bytes

__global__ __launch_bounds__(256, 2)
void dot_kernel()
{
    extern __shared__ __half dsm[];
    __half* QrH = dsm;
    __half* QrL = QrH + DQT;
    __half* QtH = QrL + DQT;
    __half* QtL = QtH + DQT;
    __half* KrH = QtL + DQT;
    __half* KrL = KrH + DKT;
    __half* KtH = KrL + DKT;
    __half* KtL = KtH + DKT;

    const int hb = blockIdx.z;
    const int mBase = blockIdx.x * 64, lBase = blockIdx.y * 128;
    const int mblk = blockIdx.x;
    const int tid = threadIdx.x;
    const int wid = tid >> 5, lane = tid & 31;
    const int r = lane >> 2, c = lane & 3;
    const int lr = lane & 7, g = lane >> 3;

    const __half* gq[4] = { g_QrHi + ((size_t)hb*Ld + lBase)*Kd, g_QrLo + ((size_t)hb*Ld + lBase)*Kd,
                            g_QtHi + ((size_t)hb*Ld + lBase)*Kd, g_QtLo + ((size_t)hb*Ld + lBase)*Kd };
    const __half* gk[4] = { g_KrHi + ((size_t)hb*Md + mBase)*Kd, g_KrLo + ((size_t)hb*Md + mBase)*Kd,
                            g_KtHi + ((size_t)hb*Md + mBase)*Kd, g_KtLo + ((size_t)hb*Md + mBase)*Kd };
    __half* sq[4] = { QrH, QrL, QtH, QtL };
    __half* sk[4] = { KrH, KrL, KtH, KtL };

    // async loads: Q tiles 128 rows x 8 chunks, K tiles 64 x 8
    #pragma unroll
    for (int s = 0; s < 4; s++) {
        uint32_t qb = smem_u32(sq[s]);
        #pragma unroll
        for (int p = 0; p < 4; p++) {
            int id = tid + p * 256;
            int row = id >> 3, ch = id & 7;
            CP_ASYNC16(qb + (uint32_t)(row * DST + ch * 8) * 2, gq[s] + (size_t)row * Kd + ch * 8);
        }
        uint32_t kb = smem_u32(sk[s]);
        #pragma unroll
        for (int p = 0; p < 2; p++) {
            int id = tid + p * 256;
            int row = id >> 3, ch = id & 7;
            CP_ASYNC16(kb + (uint32_t)(row * DST + ch * 8) * 2, gk[s] + (size_t)row * Kd + ch * 8);
        }
    }
    CP_COMMIT();
    CP_WAIT0();
    __syncthreads();

    float accR[8][4] = {}, accT[8][4] = {};

    const int la = wid * 16;
    // ldmatrix offsets (bytes): A frag (g&1 -> +8 rows, g>>1 -> +8 cols)
    const uint32_t aoff = (uint32_t)((la + lr + ((g & 1) << 3)) * DST + ((g >> 1) << 3)) * 2;
    // B frag (g>>1 -> +8 n-rows, g&1 -> +8 cols)
    const uint32_t boff = (uint32_t)((lr + ((g >> 1) << 3)) * DST + ((g & 1) << 3)) * 2;
    const uint32_t uQrH = smem_u32(QrH), uQrL = smem_u32(QrL);
    const uint32_t uQtH = smem_u32(QtH), uQtL = smem_u32(QtL);
    const uint32_t uKrH = smem_u32(KrH), uKrL = smem_u32(KrL);
    const uint32_t uKtH = smem_u32(KtH), uKtL = smem_u32(KtL);

    #pragma unroll
    for (int ks = 0; ks < 4; ks++) {
        const uint32_t ko = ks * 32;   // 16 halves = 32 bytes
        uint32_t qrh[4], qrl[4], qth[4], qtl[4];
        ldsm_x4(qrh, uQrH + aoff + ko);
        ldsm_x4(qrl, uQrL + aoff + ko);
        ldsm_x4(qth, uQtH + aoff + ko);
        ldsm_x4(qtl, uQtL + aoff + ko);
        #pragma unroll
        for (int np = 0; np < 4; np++) {
            const uint32_t no = (uint32_t)(np * 16 * DST) * 2;
            uint32_t krh[4], krl[4], kth[4], ktl[4];
            ldsm_x4(krh, uKrH + boff + no + ko);
            ldsm_x4(krl, uKrL + boff + no + ko);
            ldsm_x4(kth, uKtH + boff + no + ko);
            ldsm_x4(ktl, uKtL + boff + no + ko);
            #pragma unroll
            for (int half_nt = 0; half_nt < 2; half_nt++) {
                int nt = np * 2 + half_nt;
                uint32_t b0 = half_nt * 2, b1 = half_nt * 2 + 1;
                mma_f16(accR[nt], qrh[0], qrh[1], qrh[2], qrh[3], krh[b0], krh[b1]);
                mma_f16(accR[nt], qrh[0], qrh[1], qrh[2], qrh[3], krl[b0], krl[b1]);
                mma_f16(accR[nt], qrl[0], qrl[1], qrl[2], qrl[3], krh[b0], krh[b1]);
                mma_f16(accT[nt], qth[0], qth[1], qth[2], qth[3], kth[b0], kth[b1]);
                mma_f16(accT[nt], qth[0], qth[1], qth[2], qth[3], ktl[b0], ktl[b1]);
                mma_f16(accT[nt], qtl[0], qtl[1], qtl[2], qtl[3], kth[b0], kth[b1]);
            }
        }
    }

    // Epilogue: write S (fp32) + partial maxes
    const int l0 = lBase + la + r;
    const int l1 = l0 + 8;
    float* sR0 = g_Srgb + ((size_t)hb * Ld + l0) * Md + mBase;
    float* sR1 = g_Srgb + ((size_t)hb * Ld + l1) * Md + mBase;
    float* sT0 = g_St   + ((size_t)hb * Ld + l0) * Md + mBase;
    float* sT1 = g_St   + ((size_t)hb * Ld + l1) * Md + mBase;

    float p1a = -1e30f, p1b = -1e30f, p2a = -1e30f, p2b = -1e30f, p3a = -1e30f, p3b = -1e30f;
    #pragma unroll
    for (int nt = 0; nt < 8; nt++) {
        int col = nt * 8 + 2 * c;
        *reinterpret_cast<float2*>(sR0 + col) = make_float2(accR[nt][0], accR[nt][1]);
        *reinterpret_cast<float2*>(sR1 + col) = make_float2(accR[nt][2], accR[nt][3]);
        *reinterpret_cast<float2*>(sT0 + col) = make_float2(accT[nt][0], accT[nt][1]);
        *reinterpret_cast<float2*>(sT1 + col) = make_float2(accT[nt][2], accT[nt][3]);
        p1a = fmaxf(p1a, fmaxf(accR[nt][0], accR[nt][1]));
        p1b = fmaxf(p1b, fmaxf(accR[nt][2], accR[nt][3]));
        p2a = fmaxf(p2a, fmaxf(accT[nt][0], accT[nt][1]));
        p2b = fmaxf(p2b, fmaxf(accT[nt][2], accT[nt][3]));
        p3a = fmaxf(p3a, fmaxf(accR[nt][0]*accT[nt][0], accR[nt][1]*accT[nt][1]));
        p3b = fmaxf(p3b, fmaxf(accR[nt][2]*accT[nt][2], accR[nt][3]*accT[nt][3]));
    }
    #pragma unroll
    for (int o = 1; o <= 2; o <<= 1) {
        p1a = fmaxf(p1a, __shfl_xor_sync(0xffffffffu, p1a, o));
        p1b = fmaxf(p1b, __shfl_xor_sync(0xffffffffu, p1b, o));
        p2a = fmaxf(p2a, __shfl_xor_sync(0xffffffffu, p2a, o));
        p2b = fmaxf(p2b, __shfl_xor_sync(0xffffffffu, p2b, o));
        p3a = fmaxf(p3a, __shfl_xor_sync(0xffffffffu, p3a, o));
        p3b = fmaxf(p3b, __shfl_xor_sync(0xffffffffu, p3b, o));
    }
    if (c == 0) {
        size_t ra = (size_t)hb * Ld + l0;
        size_t rb = (size_t)hb * Ld + l1;
        g_pmax[ra*96 +      mblk] = p1a;  g_pmax[rb*96 +      mblk] = p1b;
        g_pmax[ra*96 + 32 + mblk] = p2a;  g_pmax[rb*96 + 32 + mblk] = p2b;
        g_pmax[ra*96 + 64 + mblk] = p3a;  g_pmax[rb*96 + 64 + mblk] = p3b;
    }
}

// =====================================================================
// Kernel 3: stats — reduce partial maxes, one pass ex2.f16x2, fp32 sums.
// =====================================================================
__global__ __launch_bounds__(256)
void stats_kernel()
{
    const int row = blockIdx.x;
    const float* sr = g_Srgb + (size_t)row * Md;
    const float* st = g_St   + (size_t)row * Md;
    __half* pr = g_PrH + (size_t)row * Md;
    __half* pt = g_PtH + (size_t)row * Md;
    __half* px = g_PxH + (size_t)row * Md;
    const int tid = threadIdx.x;
    const int lane = tid & 31, wid = tid >> 5;
    __shared__ float smax[3];
    __shared__ float sm[8][3];

    if (wid < 3) {
        float v = g_pmax[(size_t)row * 96 + wid*32 + lane];
        #pragma unroll
        for (int o = 16; o > 0; o >>= 1)
            v = fmaxf(v, __shfl_xor_sync(0xffffffffu, v, o));
        if (lane == 0) smax[wid] = v;
    }
    __syncthreads();

    const float L2E = 1.44269504088896340736f;
    const float m1 = 100.f * smax[0], m2 = 100.f * smax[1], m3 = smax[2];
    const float c100 = 100.f * L2E;
    const float mm1 = m1 * L2E, mm2 = m2 * L2E, mm3 = m3 * L2E;

    float s1 = 0.f, s2 = 0.f, s3 = 0.f;
    #pragma unroll
    for (int it = 0; it < 2; it++) {
        int i = (tid + it * 256) * 4;
        float4 a = *reinterpret_cast<const float4*>(sr + i);
        float4 b = *reinterpret_cast<const float4*>(st + i);

        uint32_t u0 = h2exp2u(pack_h2(fmaf(c100, a.x, -mm1), fmaf(c100, a.y, -mm1)));
        uint32_t u1 = h2exp2u(pack_h2(fmaf(c100, a.z, -mm1), fmaf(c100, a.w, -mm1)));
        *reinterpret_cast<uint2*>(pr + i) = make_uint2(u0, u1);
        float2 f0 = h2f2(u0), f1 = h2f2(u1);
        s1 += (f0.x + f0.y) + (f1.x + f1.y);

        u0 = h2exp2u(pack_h2(fmaf(c100, b.x, -mm2), fmaf(c100, b.y, -mm2)));
        u1 = h2exp2u(pack_h2(fmaf(c100, b.z, -mm2), fmaf(c100, b.w, -mm2)));
        *reinterpret_cast<uint2*>(pt + i) = make_uint2(u0, u1);
        f0 = h2f2(u0); f1 = h2f2(u1);
        s2 += (f0.x + f0.y) + (f1.x + f1.y);

        u0 = h2exp2u(pack_h2(fmaf(L2E, a.x*b.x, -mm3), fmaf(L2E, a.y*b.y, -mm3)));
        u1 = h2exp2u(pack_h2(fmaf(L2E, a.z*b.z, -mm3), fmaf(L2E, a.w*b.w, -mm3)));
        *reinterpret_cast<uint2*>(px + i) = make_uint2(u0, u1);
        f0 = h2f2(u0); f1 = h2f2(u1);
        s3 += (f0.x + f0.y) + (f1.x + f1.y);
    }
    #pragma unroll
    for (int o = 16; o > 0; o >>= 1) {
        s1 += __shfl_xor_sync(0xffffffffu, s1, o);
        s2 += __shfl_xor_sync(0xffffffffu, s2, o);
        s3 += __shfl_xor_sync(0xffffffffu, s3, o);
    }
    if (lane == 0) { sm[wid][0] = s1; sm[wid][1] = s2; sm[wid][2] = s3; }
    __syncthreads();
    if (tid == 0) {
        s1 = s2 = s3 = 0.f;
        #pragma unroll
        for (int w = 0; w < 8; w++) { s1 += sm[w][0]; s2 += sm[w][1]; s3 += sm[w][2]; }
        float* o = g_stats + (size_t)row * 6;
        o[0] = m1; o[1] = s1; o[2] = m2; o[3] = s2; o[4] = m3; o[5] = s3;
    }
}

// =====================================================================
// Kernel 4: attend, fp16 mma + cp.async double buffer + ldmatrix frags.
// grid: (F/64, L/64, HB), block 256, dynamic smem 51200 B
// =====================================================================
#define AST    40
#define ATILE  (64*AST)
#define ASTAGE (5*ATILE)
#define ATT_SMEM (2*ASTAGE*2)

__global__ __launch_bounds__(256, 2)
void attend_mma_kernel(float* __restrict__ out)
{
    extern __shared__ __half ash[];
    const int hb = blockIdx.z;
    const int h  = hb / Bd, b = hb % Bd;
    const int fBase = blockIdx.x * 64, lBase = blockIdx.y * 64;
    const int tid = threadIdx.x;
    const int wid = tid >> 5, lane = tid & 31;
    const int wl = wid & 3, wf = wid >> 2;
    const int r = lane >> 2, c = lane & 3;
    const int lr = lane & 7, g = lane >> 3;

    const __half* s0 = g_PrH + ((size_t)hb * Ld + lBase) * Md;
    const __half* s1 = g_PtH + ((size_t)hb * Ld + lBase) * Md;
    const __half* s2 = g_PxH + ((size_t)hb * Ld + lBase) * Md;
    const __half* s3 = g_VrT + ((size_t)(b * Fd + fBase)) * Md;
    const __half* s4 = g_VtT + ((size_t)(b * Fd + fBase)) * Md;

    const uint32_t sbase = smem_u32(ash);
    const int frow = tid >> 2, fseg = tid & 3;
    const uint32_t dlocal = (uint32_t)(frow * AST + fseg * 8) * 2;

    // ldmatrix offsets within a tile (bytes)
    const uint32_t aoff = (uint32_t)((wl*16 + lr + ((g & 1) << 3)) * AST + ((g >> 1) << 3)) * 2;
    const uint32_t boff = (uint32_t)((wf*32 + lr + ((g >> 1) << 3)) * AST + ((g & 1) << 3)) * 2;

    float acc[4][4][4] = {};

    {
        size_t go = (size_t)frow * Md + fseg * 8;
        uint32_t dst = sbase + dlocal;
        CP_ASYNC16(dst + 0*ATILE*2, s0 + go);
        CP_ASYNC16(dst + 1*ATILE*2, s1 + go);
        CP_ASYNC16(dst + 2*ATILE*2, s2 + go);
        CP_ASYNC16(dst + 3*ATILE*2, s3 + go);
        CP_ASYNC16(dst + 4*ATILE*2, s4 + go);
    }
    CP_COMMIT();

    for (int cc = 0; cc < Md/32; cc++) {
        if (cc + 1 < Md/32) {
            size_t go = (size_t)frow * Md + (cc + 1) * 32 + fseg * 8;
            uint32_t dst = sbase + (uint32_t)(((cc + 1) & 1) * ASTAGE) * 2 + dlocal;
            CP_ASYNC16(dst + 0*ATILE*2, s0 + go);
            CP_ASYNC16(dst + 1*ATILE*2, s1 + go);
            CP_ASYNC16(dst + 2*ATILE*2, s2 + go);
            CP_ASYNC16(dst + 3*ATILE*2, s3 + go);
            CP_ASYNC16(dst + 4*ATILE*2, s4 + go);
        }
        CP_COMMIT();
        CP_WAIT1();
        __syncthreads();

        const uint32_t stg = sbase + (uint32_t)((cc & 1) * ASTAGE) * 2;
        const uint32_t uPr = stg;
        const uint32_t uPt = stg + ATILE*2;
        const uint32_t uPx = stg + 2*ATILE*2;
        const uint32_t uVr = stg + 3*ATILE*2;
        const uint32_t uVt = stg + 4*ATILE*2;

        #pragma unroll
        for (int ks = 0; ks < 2; ks++) {
            const uint32_t ko = ks * 32;
            uint32_t ar[4], at[4], ax[4];
            ldsm_x4(ar, uPr + aoff + ko);
            ldsm_x4(at, uPt + aoff + ko);
            ldsm_x4(ax, uPx + aoff + ko);
            #pragma unroll
            for (int np = 0; np < 2; np++) {
                const uint32_t no = (uint32_t)(np * 16 * AST) * 2;
                uint32_t vr[4], vt[4];
                ldsm_x4(vr, uVr + boff + no + ko);
                ldsm_x4(vt, uVt + boff + no + ko);
                #pragma unroll
                for (int hn = 0; hn < 2; hn++) {
                    int nt = np * 2 + hn;
                    uint32_t b0 = hn * 2, b1 = hn * 2 + 1;
                    mma_f16(acc[0][nt], ar[0], ar[1], ar[2], ar[3], vr[b0], vr[b1]);
                    mma_f16(acc[1][nt], at[0], at[1], at[2], at[3], vt[b0], vt[b1]);
                    mma_f16(acc[2][nt], ax[0], ax[1], ax[2], ax[3], vt[b0], vt[b1]);
                    mma_f16(acc[3][nt], ax[0], ax[1], ax[2], ax[3], vr[b0], vr[b1]);
                }
            }
        }
        __syncthreads();
    }

    const size_t OSZ = (size_t)Ld * Bd * HFd;
    const int l0 = lBase + wl * 16 + r;
    const int l1 = l0 + 8;
    const float* st0 = g_stats + ((size_t)hb * Ld + l0) * 6;
    const float* st1 = g_stats + ((size_t)hb * Ld + l1) * 6;
    const float inv0[4] = {1.f/st0[1], 1.f/st0[3], 1.f/st0[5], 1.f/st0[5]};
    const float inv1[4] = {1.f/st1[1], 1.f/st1[3], 1.f/st1[5], 1.f/st1[5]};
    const size_t base0 = ((size_t)l0 * Bd + b) * HFd + (size_t)h * Fd;
    const size_t base1 = ((size_t)l1 * Bd + b) * HFd + (size_t)h * Fd;
    #pragma unroll
    for (int d = 0; d < 4; d++) {
        #pragma unroll
        for (int nt = 0; nt < 4; nt++) {
            int f = fBase + wf * 32 + nt * 8 + 2 * c;
            *reinterpret_cast<float2*>(out + d*OSZ + base0 + f) =
                make_float2(acc[d][nt][0] * inv0[d], acc[d][nt][1] * inv0[d]);
            *reinterpret_cast<float2*>(out + d*OSZ + base1 + f) =
                make_float2(acc[d][nt][2] * inv1[d], acc[d][nt][3] * inv1[d]);
        }
    }
}

// =====================================================================
extern "C" void kernel_launch(void* const* d_in, const int* in_sizes, int n_in,
                              void* d_out, int out_size)
{
    const float* rgbquery  = (const float*)d_in[0];
    const float* rgbkey    = (const float*)d_in[1];
    const float* rgbvalue  = (const float*)d_in[2];
    const float* tquery    = (const float*)d_in[3];
    const float* tkey      = (const float*)d_in[4];
    const float* tvalue    = (const float*)d_in[5];
    const float* fusekey   = (const float*)d_in[6];
    const float* fusevalue = (const float*)d_in[7];
    const float* WK_w      = (const float*)d_in[8];
    const float* WK_b      = (const float*)d_in[9];
    float* out = (float*)d_out;

    cudaFuncSetAttribute(dot_kernel, cudaFuncAttributeMaxDynamicSharedMemorySize, DOT_SMEM);
    cudaFuncSetAttribute(attend_mma_kernel, cudaFuncAttributeMaxDynamicSharedMemorySize, ATT_SMEM);

    vtrans_kernel<<<dim3(Md/64, Fd/64, Bd*2), 256>>>(rgbvalue, tvalue, fusevalue);
    proj_kernel<<<dim3(384, Hd), 256>>>(rgbquery, tquery, rgbkey, tkey, fusekey, WK_w, WK_b);
    dot_kernel<<<dim3(Md/64, Ld/128, HBd), 256, DOT_SMEM>>>();
    stats_kernel<<<HBd*Ld, 256>>>();
    attend_mma_kernel<<<dim3(Fd/64, Ld/64, HBd), 256, ATT_SMEM>>>(out);
}

// round 9
// speedup vs baseline: 4.5985x; 1.1613x over previous
#include <cuda_runtime.h>
#include <cuda_fp16.h>
#include <cstdint>
#include <math.h>

// Problem constants
#define Ld  1024
#define Bd  4
#define Fd  512
#define Hd  8
#define Kd  64
#define Md  2048          // Lk + Lfuse
#define HBd (Hd*Bd)       // 32
#define HFd (Hd*Fd)       // 4096

// ---------------- scratch (device globals; no allocs allowed) ----------------
__device__ __half g_XHi[(size_t)5*4096*512], g_XLo[(size_t)5*4096*512]; // inputs split
__device__ __half g_WHi[512*512], g_WLo[512*512];                       // WK_w split
__device__ __half g_QrHi[HBd*Ld*Kd], g_QrLo[HBd*Ld*Kd];   // Q/K in split fp16
__device__ __half g_QtHi[HBd*Ld*Kd], g_QtLo[HBd*Ld*Kd];
__device__ __half g_KrHi[HBd*Md*Kd], g_KrLo[HBd*Md*Kd];
__device__ __half g_KtHi[HBd*Md*Kd], g_KtLo[HBd*Md*Kd];
__device__ float  g_Srgb[(size_t)HBd*Ld*Md];     // raw dots (fp32)
__device__ float  g_St  [(size_t)HBd*Ld*Md];
__device__ __half g_PrH[(size_t)HBd*Ld*Md];      // unnormalized softmax numerators (half)
__device__ __half g_PtH[(size_t)HBd*Ld*Md];
__device__ __half g_PxH[(size_t)HBd*Ld*Md];
__device__ __half g_VrT[(size_t)Bd*Fd*Md];       // V^T half: [b][f][m]
__device__ __half g_VtT[(size_t)Bd*Fd*Md];
__device__ float  g_pmax[(size_t)HBd*Ld*96];     // per-row partial maxes [3][32 mblks]
__device__ float  g_stats[HBd*Ld*6];

// ---------------- mma / ldmatrix / exp2 / cp.async helpers ----------------
__device__ __forceinline__ void mma_f16(float* c,
                                        uint32_t a0, uint32_t a1, uint32_t a2, uint32_t a3,
                                        uint32_t b0, uint32_t b1) {
    asm volatile(
        "mma.sync.aligned.m16n8k16.row.col.f32.f16.f16.f32 "
        "{%0,%1,%2,%3}, {%4,%5,%6,%7}, {%8,%9}, {%0,%1,%2,%3};"
        : "+f"(c[0]), "+f"(c[1]), "+f"(c[2]), "+f"(c[3])
        : "r"(a0), "r"(a1), "r"(a2), "r"(a3), "r"(b0), "r"(b1));
}
__device__ __forceinline__ void ldsm_x4(uint32_t* r, uint32_t addr) {
    asm volatile("ldmatrix.sync.aligned.m8n8.x4.shared.b16 {%0,%1,%2,%3}, [%4];"
                 : "=r"(r[0]), "=r"(r[1]), "=r"(r[2]), "=r"(r[3]) : "r"(addr));
}
__device__ __forceinline__ uint32_t h2exp2u(uint32_t x) {
    uint32_t r; asm("ex2.approx.f16x2 %0, %1;" : "=r"(r) : "r"(x)); return r;
}
__device__ __forceinline__ uint32_t pack_h2(float a, float b) {
    __half2 h = __floats2half2_rn(a, b);
    return *reinterpret_cast<uint32_t*>(&h);
}
__device__ __forceinline__ float2 h2f2(uint32_t u) {
    __half2 h = *reinterpret_cast<__half2*>(&u);
    return __half22float2(h);
}
__device__ __forceinline__ uint32_t smem_u32(const void* p) {
    uint32_t a;
    asm("{ .reg .u64 t; cvta.to.shared.u64 t, %1; cvt.u32.u64 %0, t; }" : "=r"(a) : "l"(p));
    return a;
}
#define CP_ASYNC16(dst, src) \
    asm volatile("cp.async.ca.shared.global [%0], [%1], 16;" :: "r"(dst), "l"(src) : "memory")
#define CP_COMMIT() asm volatile("cp.async.commit_group;" ::: "memory")
#define CP_WAIT1()  asm volatile("cp.async.wait_group 1;" ::: "memory")
#define CP_WAIT0()  asm volatile("cp.async.wait_group 0;" ::: "memory")

// =====================================================================
// Kernel A: split inputs + W into fp16 hi/lo pairs.
// grid: (1024, 6), block 256. y=0..4 -> X sources (4096x512), y=5 -> W.
// =====================================================================
__global__ __launch_bounds__(256)
void split_kernel(const float* __restrict__ q0, const float* __restrict__ q1,
                  const float* __restrict__ k0p, const float* __restrict__ k1p,
                  const float* __restrict__ kf,  const float* __restrict__ w)
{
    const int y = blockIdx.y;
    const float* srcs[6] = {q0, q1, k0p, k1p, kf, w};
    const float* src = srcs[y];
    const int N = (y == 5) ? (512*512) : (4096*512);
    const int el = (blockIdx.x * 256 + threadIdx.x) * 8;
    if (el >= N) return;
    __half* dHi = (y == 5) ? g_WHi : g_XHi + (size_t)y * 4096 * 512;
    __half* dLo = (y == 5) ? g_WLo : g_XLo + (size_t)y * 4096 * 512;

    float4 a = *reinterpret_cast<const float4*>(src + el);
    float4 b = *reinterpret_cast<const float4*>(src + el + 4);
    float v[8] = {a.x, a.y, a.z, a.w, b.x, b.y, b.z, b.w};
    __half hh[8], hl[8];
    #pragma unroll
    for (int i = 0; i < 8; i++) {
        hh[i] = __float2half_rn(v[i]);
        hl[i] = __float2half_rn(v[i] - __half2float(hh[i]));
    }
    *reinterpret_cast<uint4*>(dHi + el) = *reinterpret_cast<uint4*>(hh);
    *reinterpret_cast<uint4*>(dLo + el) = *reinterpret_cast<uint4*>(hl);
}

// =====================================================================
// Kernel 0: V transpose+convert -> half [b][f][m]
// =====================================================================
__global__ __launch_bounds__(256)
void vtrans_kernel(const float* __restrict__ rgbvalue,
                   const float* __restrict__ tvalue,
                   const float* __restrict__ fusevalue)
{
    __shared__ __half T[64][66];
    const int mBase = blockIdx.x * 64, fBase = blockIdx.y * 64;
    const int b = blockIdx.z & 3, sel = blockIdx.z >> 2;
    const float* v0 = sel ? tvalue : rgbvalue;
    __half* dst = sel ? g_VtT : g_VrT;
    const int tid = threadIdx.x;

    #pragma unroll
    for (int p = 0; p < 2; p++) {
        int id = tid + p * 256;
        int m  = id >> 3;
        int f8 = (id & 7) * 8;
        int mm = mBase + m;
        const float* src = (mm < Ld) ? v0 + ((size_t)mm * Bd + b) * Fd
                                     : fusevalue + ((size_t)(mm - Ld) * Bd + b) * Fd;
        float4 x = *reinterpret_cast<const float4*>(src + fBase + f8);
        float4 y = *reinterpret_cast<const float4*>(src + fBase + f8 + 4);
        T[m][f8+0] = __float2half(x.x); T[m][f8+1] = __float2half(x.y);
        T[m][f8+2] = __float2half(x.z); T[m][f8+3] = __float2half(x.w);
        T[m][f8+4] = __float2half(y.x); T[m][f8+5] = __float2half(y.y);
        T[m][f8+6] = __float2half(y.z); T[m][f8+7] = __float2half(y.w);
    }
    __syncthreads();
    #pragma unroll
    for (int p = 0; p < 2; p++) {
        int id = tid + p * 256;
        int f  = id >> 3;
        int m8 = (id & 7) * 8;
        __half tmp[8];
        #pragma unroll
        for (int k = 0; k < 8; k++) tmp[k] = T[m8 + k][f];
        *reinterpret_cast<uint4*>(dst + ((size_t)(b * Fd + fBase + f)) * Md + mBase + m8) =
            *reinterpret_cast<uint4*>(tmp);
    }
}

// =====================================================================
// Kernel 1: proj via split-fp16 mma (p = xh*wh + xh*wl + xl*wh, fp32 acc)
// + bias + L2 norm; writes Q/K as half hi/lo split.
// Block: 128 rows x 64 cols, K=512 in 8 chunks. 8 warps, each 16r x 64c.
// grid: (192, 8): bx<32 Qr, <64 Qt, <128 Kr(+fuse), else Kt(+fuse).
// =====================================================================
#define PST 72
#define PXT (128*PST)
#define PWT (64*PST)
#define PROJ_SMEM ((2*PXT + 2*PWT)*2)   // 55296 bytes

__global__ __launch_bounds__(256)
void proj_mma_kernel(const float* __restrict__ bias)
{
    extern __shared__ __half psm[];
    __half* XH = psm;
    __half* XL = XH + PXT;
    __half* WH = XL + PXT;
    __half* WL = WH + PWT;

    const int bx = blockIdx.x, h = blockIdx.y;
    const int tid = threadIdx.x;
    const int wid = tid >> 5, lane = tid & 31;
    const int r = lane >> 2, c = lane & 3;
    const int lr = lane & 7, g = lane >> 3;

    int dest, rb;
    if (bx < 32)       { dest = 0; rb = bx * 128; }
    else if (bx < 64)  { dest = 1; rb = (bx - 32) * 128; }
    else if (bx < 128) { dest = 2; rb = (bx - 64) * 128; }
    else               { dest = 3; rb = (bx - 128) * 128; }

    int srcIdx, srow;
    if (dest == 0)      { srcIdx = 0; srow = rb; }
    else if (dest == 1) { srcIdx = 1; srow = rb; }
    else if (dest == 2) { srcIdx = (rb < 4096) ? 2 : 4; srow = (rb < 4096) ? rb : rb - 4096; }
    else                { srcIdx = (rb < 4096) ? 3 : 4; srow = (rb < 4096) ? rb : rb - 4096; }

    const __half* xHi = g_XHi + (size_t)srcIdx * 4096 * 512 + (size_t)srow * 512;
    const __half* xLo = g_XLo + (size_t)srcIdx * 4096 * 512 + (size_t)srow * 512;
    const __half* wHi = g_WHi + (size_t)h * 64 * 512;
    const __half* wLo = g_WLo + (size_t)h * 64 * 512;

    __half *oHi, *oLo;
    int Lx;
    if (dest == 0)      { oHi = g_QrHi; oLo = g_QrLo; Lx = Ld; }
    else if (dest == 1) { oHi = g_QtHi; oLo = g_QtLo; Lx = Ld; }
    else if (dest == 2) { oHi = g_KrHi; oLo = g_KrLo; Lx = Md; }
    else                { oHi = g_KtHi; oLo = g_KtLo; Lx = Md; }

    const uint32_t uXH = smem_u32(XH), uXL = smem_u32(XL);
    const uint32_t uWH = smem_u32(WH), uWL = smem_u32(WL);
    const uint32_t aoff = (uint32_t)((wid*16 + lr + ((g & 1) << 3)) * PST + ((g >> 1) << 3)) * 2;
    const uint32_t boff = (uint32_t)((lr + ((g >> 1) << 3)) * PST + ((g & 1) << 3)) * 2;

    float acc[8][4] = {};

    for (int kc = 0; kc < 8; kc++) {
        const int k0 = kc * 64;
        #pragma unroll
        for (int p = 0; p < 4; p++) {
            int id = tid + p * 256;
            int row = id >> 3, seg = id & 7;
            uint32_t d = (uint32_t)(row * PST + seg * 8) * 2;
            CP_ASYNC16(uXH + d, xHi + (size_t)row * 512 + k0 + seg * 8);
            CP_ASYNC16(uXL + d, xLo + (size_t)row * 512 + k0 + seg * 8);
        }
        #pragma unroll
        for (int p = 0; p < 2; p++) {
            int id = tid + p * 256;
            int row = id >> 3, seg = id & 7;
            uint32_t d = (uint32_t)(row * PST + seg * 8) * 2;
            CP_ASYNC16(uWH + d, wHi + (size_t)row * 512 + k0 + seg * 8);
            CP_ASYNC16(uWL + d, wLo + (size_t)row * 512 + k0 + seg * 8);
        }
        CP_COMMIT();
        CP_WAIT0();
        __syncthreads();

        #pragma unroll
        for (int ks = 0; ks < 4; ks++) {
            const uint32_t ko = ks * 32;
            uint32_t ah[4], al[4];
            ldsm_x4(ah, uXH + aoff + ko);
            ldsm_x4(al, uXL + aoff + ko);
            #pragma unroll
            for (int np = 0; np < 4; np++) {
                const uint32_t no = (uint32_t)(np * 16 * PST) * 2;
                uint32_t bh[4], bl[4];
                ldsm_x4(bh, uWH + boff + no + ko);
                ldsm_x4(bl, uWL + boff + no + ko);
                #pragma unroll
                for (int hn = 0; hn < 2; hn++) {
                    int nt = np * 2 + hn;
                    uint32_t b0 = hn * 2, b1 = hn * 2 + 1;
                    mma_f16(acc[nt], ah[0], ah[1], ah[2], ah[3], bh[b0], bh[b1]);
                    mma_f16(acc[nt], ah[0], ah[1], ah[2], ah[3], bl[b0], bl[b1]);
                    mma_f16(acc[nt], al[0], al[1], al[2], al[3], bh[b0], bh[b1]);
                }
            }
        }
        __syncthreads();
    }

    // bias (zeros per setup; kept for fidelity)
    #pragma unroll
    for (int nt = 0; nt < 8; nt++) {
        int col = nt * 8 + 2 * c;
        float b0 = bias[h*64 + col], b1 = bias[h*64 + col + 1];
        acc[nt][0] += b0; acc[nt][2] += b0;
        acc[nt][1] += b1; acc[nt][3] += b1;
    }

    // per-row L2 norm (reduce over the 4 c-lanes)
    float s0 = 0.f, s1 = 0.f;
    #pragma unroll
    for (int nt = 0; nt < 8; nt++) {
        s0 += acc[nt][0]*acc[nt][0] + acc[nt][1]*acc[nt][1];
        s1 += acc[nt][2]*acc[nt][2] + acc[nt][3]*acc[nt][3];
    }
    s0 += __shfl_xor_sync(0xffffffffu, s0, 1);
    s0 += __shfl_xor_sync(0xffffffffu, s0, 2);
    s1 += __shfl_xor_sync(0xffffffffu, s1, 1);
    s1 += __shfl_xor_sync(0xffffffffu, s1, 2);
    const float inv0 = 1.0f / fmaxf(sqrtf(s0), 1e-12f);
    const float inv1 = 1.0f / fmaxf(sqrtf(s1), 1e-12f);

    const int gr0 = rb + wid * 16 + r;
    const int gr1 = gr0 + 8;
    const int l0 = gr0 >> 2, bb0 = gr0 & 3;
    const int l1 = gr1 >> 2, bb1 = gr1 & 3;
    const size_t off0 = ((size_t)(h*4 + bb0) * Lx + l0) * 64;
    const size_t off1 = ((size_t)(h*4 + bb1) * Lx + l1) * 64;

    #pragma unroll
    for (int nt = 0; nt < 8; nt++) {
        int col = nt * 8 + 2 * c;
        float v0 = acc[nt][0] * inv0, v1 = acc[nt][1] * inv0;
        __half h0 = __float2half_rn(v0), h1 = __float2half_rn(v1);
        __half e0 = __float2half_rn(v0 - __half2float(h0));
        __half e1 = __float2half_rn(v1 - __half2float(h1));
        *reinterpret_cast<__half2*>(oHi + off0 + col) = __halves2half2(h0, h1);
        *reinterpret_cast<__half2*>(oLo + off0 + col) = __halves2half2(e0, e1);
        float w0 = acc[nt][2] * inv1, w1 = acc[nt][3] * inv1;
        __half j0 = __float2half_rn(w0), j1 = __float2half_rn(w1);
        __half f0 = __float2half_rn(w0 - __half2float(j0));
        __half f1 = __float2half_rn(w1 - __half2float(j1));
        *reinterpret_cast<__half2*>(oHi + off1 + col) = __halves2half2(j0, j1);
        *reinterpret_cast<__half2*>(oLo + off1 + col) = __halves2half2(f0, f1);
    }
}

// =====================================================================
// Kernel 2: dot via split-fp16 mma: s = qh*kh + qh*kl + ql*kh (fp32 acc).
// Block: 128l x 64m, K=64 one-shot. Writes fp32 S + partial maxes.
// grid: (Md/64, Ld/128, HBd), block 256, dynamic smem 110592 B
// =====================================================================
#define DST 72
#define DQT (128*DST)
#define DKT (64*DST)
#define DOT_SMEM ((4*DQT + 4*DKT)*2)

__global__ __launch_bounds__(256, 2)
void dot_kernel()
{
    extern __shared__ __half dsm[];
    __half* QrH = dsm;
    __half* QrL = QrH + DQT;
    __half* QtH = QrL + DQT;
    __half* QtL = QtH + DQT;
    __half* KrH = QtL + DQT;
    __half* KrL = KrH + DKT;
    __half* KtH = KrL + DKT;
    __half* KtL = KtH + DKT;

    const int hb = blockIdx.z;
    const int mBase = blockIdx.x * 64, lBase = blockIdx.y * 128;
    const int mblk = blockIdx.x;
    const int tid = threadIdx.x;
    const int wid = tid >> 5, lane = tid & 31;
    const int r = lane >> 2, c = lane & 3;
    const int lr = lane & 7, g = lane >> 3;

    const __half* gq[4] = { g_QrHi + ((size_t)hb*Ld + lBase)*Kd, g_QrLo + ((size_t)hb*Ld + lBase)*Kd,
                            g_QtHi + ((size_t)hb*Ld + lBase)*Kd, g_QtLo + ((size_t)hb*Ld + lBase)*Kd };
    const __half* gk[4] = { g_KrHi + ((size_t)hb*Md + mBase)*Kd, g_KrLo + ((size_t)hb*Md + mBase)*Kd,
                            g_KtHi + ((size_t)hb*Md + mBase)*Kd, g_KtLo + ((size_t)hb*Md + mBase)*Kd };
    __half* sq[4] = { QrH, QrL, QtH, QtL };
    __half* sk[4] = { KrH, KrL, KtH, KtL };

    #pragma unroll
    for (int s = 0; s < 4; s++) {
        uint32_t qb = smem_u32(sq[s]);
        #pragma unroll
        for (int p = 0; p < 4; p++) {
            int id = tid + p * 256;
            int row = id >> 3, ch = id & 7;
            CP_ASYNC16(qb + (uint32_t)(row * DST + ch * 8) * 2, gq[s] + (size_t)row * Kd + ch * 8);
        }
        uint32_t kb = smem_u32(sk[s]);
        #pragma unroll
        for (int p = 0; p < 2; p++) {
            int id = tid + p * 256;
            int row = id >> 3, ch = id & 7;
            CP_ASYNC16(kb + (uint32_t)(row * DST + ch * 8) * 2, gk[s] + (size_t)row * Kd + ch * 8);
        }
    }
    CP_COMMIT();
    CP_WAIT0();
    __syncthreads();

    float accR[8][4] = {}, accT[8][4] = {};

    const int la = wid * 16;
    const uint32_t aoff = (uint32_t)((la + lr + ((g & 1) << 3)) * DST + ((g >> 1) << 3)) * 2;
    const uint32_t boff = (uint32_t)((lr + ((g >> 1) << 3)) * DST + ((g & 1) << 3)) * 2;
    const uint32_t uQrH = smem_u32(QrH), uQrL = smem_u32(QrL);
    const uint32_t uQtH = smem_u32(QtH), uQtL = smem_u32(QtL);
    const uint32_t uKrH = smem_u32(KrH), uKrL = smem_u32(KrL);
    const uint32_t uKtH = smem_u32(KtH), uKtL = smem_u32(KtL);

    #pragma unroll
    for (int ks = 0; ks < 4; ks++) {
        const uint32_t ko = ks * 32;
        uint32_t qrh[4], qrl[4], qth[4], qtl[4];
        ldsm_x4(qrh, uQrH + aoff + ko);
        ldsm_x4(qrl, uQrL + aoff + ko);
        ldsm_x4(qth, uQtH + aoff + ko);
        ldsm_x4(qtl, uQtL + aoff + ko);
        #pragma unroll
        for (int np = 0; np < 4; np++) {
            const uint32_t no = (uint32_t)(np * 16 * DST) * 2;
            uint32_t krh[4], krl[4], kth[4], ktl[4];
            ldsm_x4(krh, uKrH + boff + no + ko);
            ldsm_x4(krl, uKrL + boff + no + ko);
            ldsm_x4(kth, uKtH + boff + no + ko);
            ldsm_x4(ktl, uKtL + boff + no + ko);
            #pragma unroll
            for (int half_nt = 0; half_nt < 2; half_nt++) {
                int nt = np * 2 + half_nt;
                uint32_t b0 = half_nt * 2, b1 = half_nt * 2 + 1;
                mma_f16(accR[nt], qrh[0], qrh[1], qrh[2], qrh[3], krh[b0], krh[b1]);
                mma_f16(accR[nt], qrh[0], qrh[1], qrh[2], qrh[3], krl[b0], krl[b1]);
                mma_f16(accR[nt], qrl[0], qrl[1], qrl[2], qrl[3], krh[b0], krh[b1]);
                mma_f16(accT[nt], qth[0], qth[1], qth[2], qth[3], kth[b0], kth[b1]);
                mma_f16(accT[nt], qth[0], qth[1], qth[2], qth[3], ktl[b0], ktl[b1]);
                mma_f16(accT[nt], qtl[0], qtl[1], qtl[2], qtl[3], kth[b0], kth[b1]);
            }
        }
    }

    const int l0 = lBase + la + r;
    const int l1 = l0 + 8;
    float* sR0 = g_Srgb + ((size_t)hb * Ld + l0) * Md + mBase;
    float* sR1 = g_Srgb + ((size_t)hb * Ld + l1) * Md + mBase;
    float* sT0 = g_St   + ((size_t)hb * Ld + l0) * Md + mBase;
    float* sT1 = g_St   + ((size_t)hb * Ld + l1) * Md + mBase;

    float p1a = -1e30f, p1b = -1e30f, p2a = -1e30f, p2b = -1e30f, p3a = -1e30f, p3b = -1e30f;
    #pragma unroll
    for (int nt = 0; nt < 8; nt++) {
        int col = nt * 8 + 2 * c;
        *reinterpret_cast<float2*>(sR0 + col) = make_float2(accR[nt][0], accR[nt][1]);
        *reinterpret_cast<float2*>(sR1 + col) = make_float2(accR[nt][2], accR[nt][3]);
        *reinterpret_cast<float2*>(sT0 + col) = make_float2(accT[nt][0], accT[nt][1]);
        *reinterpret_cast<float2*>(sT1 + col) = make_float2(accT[nt][2], accT[nt][3]);
        p1a = fmaxf(p1a, fmaxf(accR[nt][0], accR[nt][1]));
        p1b = fmaxf(p1b, fmaxf(accR[nt][2], accR[nt][3]));
        p2a = fmaxf(p2a, fmaxf(accT[nt][0], accT[nt][1]));
        p2b = fmaxf(p2b, fmaxf(accT[nt][2], accT[nt][3]));
        p3a = fmaxf(p3a, fmaxf(accR[nt][0]*accT[nt][0], accR[nt][1]*accT[nt][1]));
        p3b = fmaxf(p3b, fmaxf(accR[nt][2]*accT[nt][2], accR[nt][3]*accT[nt][3]));
    }
    #pragma unroll
    for (int o = 1; o <= 2; o <<= 1) {
        p1a = fmaxf(p1a, __shfl_xor_sync(0xffffffffu, p1a, o));
        p1b = fmaxf(p1b, __shfl_xor_sync(0xffffffffu, p1b, o));
        p2a = fmaxf(p2a, __shfl_xor_sync(0xffffffffu, p2a, o));
        p2b = fmaxf(p2b, __shfl_xor_sync(0xffffffffu, p2b, o));
        p3a = fmaxf(p3a, __shfl_xor_sync(0xffffffffu, p3a, o));
        p3b = fmaxf(p3b, __shfl_xor_sync(0xffffffffu, p3b, o));
    }
    if (c == 0) {
        size_t ra = (size_t)hb * Ld + l0;
        size_t rb = (size_t)hb * Ld + l1;
        g_pmax[ra*96 +      mblk] = p1a;  g_pmax[rb*96 +      mblk] = p1b;
        g_pmax[ra*96 + 32 + mblk] = p2a;  g_pmax[rb*96 + 32 + mblk] = p2b;
        g_pmax[ra*96 + 64 + mblk] = p3a;  g_pmax[rb*96 + 64 + mblk] = p3b;
    }
}

// =====================================================================
// Kernel 3: stats — reduce partial maxes, one pass ex2.f16x2, fp32 sums.
// =====================================================================
__global__ __launch_bounds__(256)
void stats_kernel()
{
    const int row = blockIdx.x;
    const float* sr = g_Srgb + (size_t)row * Md;
    const float* st = g_St   + (size_t)row * Md;
    __half* pr = g_PrH + (size_t)row * Md;
    __half* pt = g_PtH + (size_t)row * Md;
    __half* px = g_PxH + (size_t)row * Md;
    const int tid = threadIdx.x;
    const int lane = tid & 31, wid = tid >> 5;
    __shared__ float smax[3];
    __shared__ float sm[8][3];

    if (wid < 3) {
        float v = g_pmax[(size_t)row * 96 + wid*32 + lane];
        #pragma unroll
        for (int o = 16; o > 0; o >>= 1)
            v = fmaxf(v, __shfl_xor_sync(0xffffffffu, v, o));
        if (lane == 0) smax[wid] = v;
    }
    __syncthreads();

    const float L2E = 1.44269504088896340736f;
    const float m1 = 100.f * smax[0], m2 = 100.f * smax[1], m3 = smax[2];
    const float c100 = 100.f * L2E;
    const float mm1 = m1 * L2E, mm2 = m2 * L2E, mm3 = m3 * L2E;

    float s1 = 0.f, s2 = 0.f, s3 = 0.f;
    #pragma unroll
    for (int it = 0; it < 2; it++) {
        int i = (tid + it * 256) * 4;
        float4 a = *reinterpret_cast<const float4*>(sr + i);
        float4 b = *reinterpret_cast<const float4*>(st + i);

        uint32_t u0 = h2exp2u(pack_h2(fmaf(c100, a.x, -mm1), fmaf(c100, a.y, -mm1)));
        uint32_t u1 = h2exp2u(pack_h2(fmaf(c100, a.z, -mm1), fmaf(c100, a.w, -mm1)));
        *reinterpret_cast<uint2*>(pr + i) = make_uint2(u0, u1);
        float2 f0 = h2f2(u0), f1 = h2f2(u1);
        s1 += (f0.x + f0.y) + (f1.x + f1.y);

        u0 = h2exp2u(pack_h2(fmaf(c100, b.x, -mm2), fmaf(c100, b.y, -mm2)));
        u1 = h2exp2u(pack_h2(fmaf(c100, b.z, -mm2), fmaf(c100, b.w, -mm2)));
        *reinterpret_cast<uint2*>(pt + i) = make_uint2(u0, u1);
        f0 = h2f2(u0); f1 = h2f2(u1);
        s2 += (f0.x + f0.y) + (f1.x + f1.y);

        u0 = h2exp2u(pack_h2(fmaf(L2E, a.x*b.x, -mm3), fmaf(L2E, a.y*b.y, -mm3)));
        u1 = h2exp2u(pack_h2(fmaf(L2E, a.z*b.z, -mm3), fmaf(L2E, a.w*b.w, -mm3)));
        *reinterpret_cast<uint2*>(px + i) = make_uint2(u0, u1);
        f0 = h2f2(u0); f1 = h2f2(u1);
        s3 += (f0.x + f0.y) + (f1.x + f1.y);
    }
    #pragma unroll
    for (int o = 16; o > 0; o >>= 1) {
        s1 += __shfl_xor_sync(0xffffffffu, s1, o);
        s2 += __shfl_xor_sync(0xffffffffu, s2, o);
        s3 += __shfl_xor_sync(0xffffffffu, s3, o);
    }
    if (lane == 0) { sm[wid][0] = s1; sm[wid][1] = s2; sm[wid][2] = s3; }
    __syncthreads();
    if (tid == 0) {
        s1 = s2 = s3 = 0.f;
        #pragma unroll
        for (int w = 0; w < 8; w++) { s1 += sm[w][0]; s2 += sm[w][1]; s3 += sm[w][2]; }
        float* o = g_stats + (size_t)row * 6;
        o[0] = m1; o[1] = s1; o[2] = m2; o[3] = s2; o[4] = m3; o[5] = s3;
    }
}

// =====================================================================
// Kernel 4: attend, fp16 mma + cp.async double buffer + ldmatrix frags.
// grid: (F/64, L/64, HB), block 256, dynamic smem 51200 B
// =====================================================================
#define AST    40
#define ATILE  (64*AST)
#define ASTAGE (5*ATILE)
#define ATT_SMEM (2*ASTAGE*2)

__global__ __launch_bounds__(256, 2)
void attend_mma_kernel(float* __restrict__ out)
{
    extern __shared__ __half ash[];
    const int hb = blockIdx.z;
    const int h  = hb / Bd, b = hb % Bd;
    const int fBase = blockIdx.x * 64, lBase = blockIdx.y * 64;
    const int tid = threadIdx.x;
    const int wid = tid >> 5, lane = tid & 31;
    const int wl = wid & 3, wf = wid >> 2;
    const int r = lane >> 2, c = lane & 3;
    const int lr = lane & 7, g = lane >> 3;

    const __half* s0 = g_PrH + ((size_t)hb * Ld + lBase) * Md;
    const __half* s1 = g_PtH + ((size_t)hb * Ld + lBase) * Md;
    const __half* s2 = g_PxH + ((size_t)hb * Ld + lBase) * Md;
    const __half* s3 = g_VrT + ((size_t)(b * Fd + fBase)) * Md;
    const __half* s4 = g_VtT + ((size_t)(b * Fd + fBase)) * Md;

    const uint32_t sbase = smem_u32(ash);
    const int frow = tid >> 2, fseg = tid & 3;
    const uint32_t dlocal = (uint32_t)(frow * AST + fseg * 8) * 2;

    const uint32_t aoff = (uint32_t)((wl*16 + lr + ((g & 1) << 3)) * AST + ((g >> 1) << 3)) * 2;
    const uint32_t boff = (uint32_t)((wf*32 + lr + ((g >> 1) << 3)) * AST + ((g & 1) << 3)) * 2;

    float acc[4][4][4] = {};

    {
        size_t go = (size_t)frow * Md + fseg * 8;
        uint32_t dst = sbase + dlocal;
        CP_ASYNC16(dst + 0*ATILE*2, s0 + go);
        CP_ASYNC16(dst + 1*ATILE*2, s1 + go);
        CP_ASYNC16(dst + 2*ATILE*2, s2 + go);
        CP_ASYNC16(dst + 3*ATILE*2, s3 + go);
        CP_ASYNC16(dst + 4*ATILE*2, s4 + go);
    }
    CP_COMMIT();

    for (int cc = 0; cc < Md/32; cc++) {
        if (cc + 1 < Md/32) {
            size_t go = (size_t)frow * Md + (cc + 1) * 32 + fseg * 8;
            uint32_t dst = sbase + (uint32_t)(((cc + 1) & 1) * ASTAGE) * 2 + dlocal;
            CP_ASYNC16(dst + 0*ATILE*2, s0 + go);
            CP_ASYNC16(dst + 1*ATILE*2, s1 + go);
            CP_ASYNC16(dst + 2*ATILE*2, s2 + go);
            CP_ASYNC16(dst + 3*ATILE*2, s3 + go);
            CP_ASYNC16(dst + 4*ATILE*2, s4 + go);
        }
        CP_COMMIT();
        CP_WAIT1();
        __syncthreads();

        const uint32_t stg = sbase + (uint32_t)((cc & 1) * ASTAGE) * 2;
        const uint32_t uPr = stg;
        const uint32_t uPt = stg + ATILE*2;
        const uint32_t uPx = stg + 2*ATILE*2;
        const uint32_t uVr = stg + 3*ATILE*2;
        const uint32_t uVt = stg + 4*ATILE*2;

        #pragma unroll
        for (int ks = 0; ks < 2; ks++) {
            const uint32_t ko = ks * 32;
            uint32_t ar[4], at[4], ax[4];
            ldsm_x4(ar, uPr + aoff + ko);
            ldsm_x4(at, uPt + aoff + ko);
            ldsm_x4(ax, uPx + aoff + ko);
            #pragma unroll
            for (int np = 0; np < 2; np++) {
                const uint32_t no = (uint32_t)(np * 16 * AST) * 2;
                uint32_t vr[4], vt[4];
                ldsm_x4(vr, uVr + boff + no + ko);
                ldsm_x4(vt, uVt + boff + no + ko);
                #pragma unroll
                for (int hn = 0; hn < 2; hn++) {
                    int nt = np * 2 + hn;
                    uint32_t b0 = hn * 2, b1 = hn * 2 + 1;
                    mma_f16(acc[0][nt], ar[0], ar[1], ar[2], ar[3], vr[b0], vr[b1]);
                    mma_f16(acc[1][nt], at[0], at[1], at[2], at[3], vt[b0], vt[b1]);
                    mma_f16(acc[2][nt], ax[0], ax[1], ax[2], ax[3], vt[b0], vt[b1]);
                    mma_f16(acc[3][nt], ax[0], ax[1], ax[2], ax[3], vr[b0], vr[b1]);
                }
            }
        }
        __syncthreads();
    }

    const size_t OSZ = (size_t)Ld * Bd * HFd;
    const int l0 = lBase + wl * 16 + r;
    const int l1 = l0 + 8;
    const float* st0 = g_stats + ((size_t)hb * Ld + l0) * 6;
    const float* st1 = g_stats + ((size_t)hb * Ld + l1) * 6;
    const float inv0[4] = {1.f/st0[1], 1.f/st0[3], 1.f/st0[5], 1.f/st0[5]};
    const float inv1[4] = {1.f/st1[1], 1.f/st1[3], 1.f/st1[5], 1.f/st1[5]};
    const size_t base0 = ((size_t)l0 * Bd + b) * HFd + (size_t)h * Fd;
    const size_t base1 = ((size_t)l1 * Bd + b) * HFd + (size_t)h * Fd;
    #pragma unroll
    for (int d = 0; d < 4; d++) {
        #pragma unroll
        for (int nt = 0; nt < 4; nt++) {
            int f = fBase + wf * 32 + nt * 8 + 2 * c;
            *reinterpret_cast<float2*>(out + d*OSZ + base0 + f) =
                make_float2(acc[d][nt][0] * inv0[d], acc[d][nt][1] * inv0[d]);
            *reinterpret_cast<float2*>(out + d*OSZ + base1 + f) =
                make_float2(acc[d][nt][2] * inv1[d], acc[d][nt][3] * inv1[d]);
        }
    }
}

// =====================================================================
extern "C" void kernel_launch(void* const* d_in, const int* in_sizes, int n_in,
                              void* d_out, int out_size)
{
    const float* rgbquery  = (const float*)d_in[0];
    const float* rgbkey    = (const float*)d_in[1];
    const float* rgbvalue  = (const float*)d_in[2];
    const float* tquery    = (const float*)d_in[3];
    const float* tkey      = (const float*)d_in[4];
    const float* tvalue    = (const float*)d_in[5];
    const float* fusekey   = (const float*)d_in[6];
    const float* fusevalue = (const float*)d_in[7];
    const float* WK_w      = (const float*)d_in[8];
    const float* WK_b      = (const float*)d_in[9];
    float* out = (float*)d_out;

    cudaFuncSetAttribute(proj_mma_kernel, cudaFuncAttributeMaxDynamicSharedMemorySize, PROJ_SMEM);
    cudaFuncSetAttribute(dot_kernel, cudaFuncAttributeMaxDynamicSharedMemorySize, DOT_SMEM);
    cudaFuncSetAttribute(attend_mma_kernel, cudaFuncAttributeMaxDynamicSharedMemorySize, ATT_SMEM);

    split_kernel<<<dim3(1024, 6), 256>>>(rgbquery, tquery, rgbkey, tkey, fusekey, WK_w);
    vtrans_kernel<<<dim3(Md/64, Fd/64, Bd*2), 256>>>(rgbvalue, tvalue, fusevalue);
    proj_mma_kernel<<<dim3(192, Hd), 256, PROJ_SMEM>>>(WK_b);
    dot_kernel<<<dim3(Md/64, Ld/128, HBd), 256, DOT_SMEM>>>();
    stats_kernel<<<HBd*Ld, 256>>>();
    attend_mma_kernel<<<dim3(Fd/64, Ld/64, HBd), 256, ATT_SMEM>>>(out);
}